// round 13
// baseline (speedup 1.0000x reference)
#include <cuda_runtime.h>
#include <cuda_fp16.h>
#include <cstdint>
#include <cstddef>

#define HWC 9216
#define EPSN 1e-5f

// ---------------- scratch (__device__ globals; no allocation) ----------------
__device__ __align__(16) __half g_y1h[75497472]; // conv1 output fp16 [128,64,9216]
__device__ float g_g2[1179648];       // gen-block intermediate [8,16,9216]
__device__ float g_tsum[512];         // sum_hw sr [8,64]
__device__ float g_T1[512];           // sum_hw tg
__device__ float g_T2[512];           // sum_hw tg^2
__device__ float g_op[8192];          // [128,64]
__device__ float g_u[8192];           // W^T opn
__device__ float g_v[8192];           // sum_hw sr*cof
__device__ float g_A1[8192];          // GN1 affine scale
__device__ float g_D1[8192];          // GN1 affine shift
__device__ float g_gn2s[8192];
__device__ float g_gn2q[8192];
__device__ float g_mstat[256];        // per-bn (mu, invstd) of msk
__device__ float g_in2s[128];
__device__ float g_in2q[128];
__device__ float2 g_pms[4608];        // per-(bn,blk) online softmax partials (m,s)
__device__ unsigned g_barc[16];       // grid-barrier counters
__device__ __align__(16) __half g_wpack[36864];   // packed fp16 conv1 weights
__device__ __align__(16) __half g_w2pack[4608];   // conv2 weights: [chunk4][tap9][n8][slot16]

// ---------------- helpers ----------------
__device__ __forceinline__ float wred(float v) {
#pragma unroll
    for (int o = 16; o > 0; o >>= 1) v += __shfl_xor_sync(0xffffffffu, v, o);
    return v;
}
__device__ __forceinline__ float bsum256(float v, float* red) {
    int t = threadIdx.x; red[t] = v; __syncthreads();
#pragma unroll
    for (int s = 128; s > 0; s >>= 1) { if (t < s) red[t] += red[t + s]; __syncthreads(); }
    float r = red[0]; __syncthreads(); return r;
}
__device__ __forceinline__ float bmax256(float v, float* red) {
    int t = threadIdx.x; red[t] = v; __syncthreads();
#pragma unroll
    for (int s = 128; s > 0; s >>= 1) { if (t < s) red[t] = fmaxf(red[t], red[t + s]); __syncthreads(); }
    float r = red[0]; __syncthreads(); return r;
}
__device__ __forceinline__ int slot_of(int c) {   // cin-slot permutation
    return 4 * ((c & 7) >> 1) + ((((c >> 3) & 1) << 1) | (c & 1));
}
// grid barrier: all 288 CTAs of k_route arrive. Residency guaranteed by occupancy.
__device__ __forceinline__ void gbar(int id) {
    __syncthreads();
    if (threadIdx.x == 0) {
        __threadfence();
        atomicAdd(&g_barc[id], 1u);
        while (*(volatile unsigned*)&g_barc[id] < 288u) __nanosleep(64);
        __threadfence();
    }
    __syncthreads();
}

// ---------------- 1: colsum (blocks 0..511) + weight packs + barrier reset -------
__global__ void k_colsum(const float* __restrict__ sr, const float* __restrict__ tg,
                         const float* __restrict__ c1w, const float* __restrict__ c2w,
                         float* __restrict__ out_loss) {
    if (blockIdx.x >= 512) {
        int idx = (blockIdx.x - 512) * 256 + threadIdx.x;   // 0..36863
        if (idx == 0) out_loss[0] = 0.f;
        if (idx < 16) g_barc[idx] = 0u;
        {   // conv1 weights
            int slot = idx & 15;
            int co = (idx >> 4) & 63;
            int rest = idx >> 10;
            int tap = rest % 9, chunk = rest / 9;
            int p = slot >> 2, pos = slot & 3;
            int cin = 2 * p + (pos & 1) + ((pos >> 1) << 3);
            g_wpack[idx] = __float2half_rn(c1w[(size_t)(co * 64 + chunk * 16 + cin) * 9 + tap]);
        }
        if (idx < 4608) {   // conv2 weights, B-fragment layout, n=0 real / n>0 zero
            int slot = idx & 15;
            int n = (idx >> 4) & 7;
            int rest = idx >> 7;               // chunk*9 + tap
            int tap = rest % 9, chunk = rest / 9;
            int p = slot >> 2, pos = slot & 3;
            int cin = 2 * p + (pos & 1) + ((pos >> 1) << 3);
            float wv = (n == 0) ? c2w[(chunk * 16 + cin) * 9 + tap] : 0.f;
            g_w2pack[idx] = __float2half_rn(wv);
        }
        return;
    }
    int bc = blockIdx.x;
    const float4* ps = (const float4*)(sr + (size_t)bc * HWC);
    const float4* pt = (const float4*)(tg + (size_t)bc * HWC);
    float s0 = 0.f, s1 = 0.f, s2 = 0.f;
    for (int i = threadIdx.x; i < 2304; i += 256) {
        float4 a = ps[i], b = pt[i];
        s0 += a.x + a.y + a.z + a.w;
        s1 += b.x + b.y + b.z + b.w;
        s2 += b.x * b.x + b.y * b.y + b.z * b.z + b.w * b.w;
    }
    __shared__ float red[256];
    s0 = bsum256(s0, red); s1 = bsum256(s1, red); s2 = bsum256(s2, red);
    if (threadIdx.x == 0) { g_tsum[bc] = s0; g_T1[bc] = s1; g_T2[bc] = s2; }
}

// ---------------- 2: fused dynamic-routing loop (persistent, grid barriers) ------
__global__ void __launch_bounds__(256, 2) k_route(
    const float* __restrict__ sr, const float* __restrict__ ww,
    const float* __restrict__ wb, const float* __restrict__ g1g,
    const float* __restrict__ g1b, float* __restrict__ extra)
{
    __shared__ float us[1024];
    __shared__ float ls[16 * 257];
    __shared__ float2 Ms[16];
    int b = blockIdx.y, blk = blockIdx.x;
    int tid = threadIdx.x;
    int hw = blk * 256 + tid;
    int w = tid >> 5, lane = tid & 31;

    // ---- C0 ----
    if (blk < 16) {
        int n = blk, bn = b * 16 + n, c = tid;
        float op = 0.f;
        if (tid < 64) ls[tid] = g_tsum[b * 64 + tid];
        __syncthreads();
        if (tid < 64) {
            const float* wr = ww + (size_t)(n * 64 + c) * 64;
            float a = 0.f;
#pragma unroll 8
            for (int cp = 0; cp < 64; cp++) a = fmaf(wr[cp], ls[cp], a);
            op = a + wb[n * 64 + c] * 9216.f;
            g_op[bn * 64 + c] = op;
            ls[64 + c] = op * op;
        }
        __syncthreads();
        if (tid == 0) {
            float s = 0.f;
            for (int i = 0; i < 64; i++) s += ls[64 + i];
            ls[128] = fmaxf(sqrtf(s), 1e-12f);
        }
        __syncthreads();
        if (tid < 64) ls[192 + c] = op / ls[128];
        __syncthreads();
        if (tid < 64) {
            float u = 0.f;
            for (int cp = 0; cp < 64; cp++) u = fmaf(ww[(size_t)(n * 64 + cp) * 64 + c], ls[192 + cp], u);
            g_u[bn * 64 + c] = u;
            g_v[bn * 64 + c] = 0.f;
        }
    }
    gbar(0);

    for (int it = 0; it < 3; it++) {
        // ---- A ----
        __syncthreads();
        for (int i = tid; i < 1024; i += 256) us[i] = g_u[b * 1024 + i];
        __syncthreads();
        float acc[16];
#pragma unroll
        for (int n = 0; n < 16; n++) acc[n] = 0.f;
        {
            const float* sp = sr + (size_t)b * 64 * HWC + hw;
            for (int c = 0; c < 64; c++) {
                float v = sp[(size_t)c * HWC];
#pragma unroll
                for (int n = 0; n < 16; n++) acc[n] = fmaf(us[n * 64 + c], v, acc[n]);
            }
        }
#pragma unroll
        for (int n = 0; n < 16; n++) ls[n * 257 + tid] = acc[n];
        __syncthreads();
#pragma unroll
        for (int nn = 0; nn < 2; nn++) {
            int n = w * 2 + nn;
            float v[8]; float mx = -1e30f;
#pragma unroll
            for (int j = 0; j < 8; j++) { v[j] = ls[n * 257 + lane + 32 * j]; mx = fmaxf(mx, v[j]); }
#pragma unroll
            for (int o = 16; o > 0; o >>= 1) mx = fmaxf(mx, __shfl_xor_sync(0xffffffffu, mx, o));
            float s = 0.f;
#pragma unroll
            for (int j = 0; j < 8; j++) s += expf(v[j] - mx);
            s = wred(s);
            if (lane == 0) g_pms[(b * 16 + n) * 36 + blk] = make_float2(mx, s);
        }
        gbar(1 + 3 * it);

        // ---- B ----
        if (tid < 16) {
            const float2* pp = g_pms + (b * 16 + tid) * 36;
            float M = -1e30f;
#pragma unroll
            for (int i = 0; i < 36; i++) M = fmaxf(M, pp[i].x);
            float S = 0.f;
#pragma unroll
            for (int i = 0; i < 36; i++) S += pp[i].y * expf(pp[i].x - M);
            Ms[tid] = make_float2(M, 1.f / S);
        }
        __syncthreads();
        for (int idx = tid; idx < 4096; idx += 256) {
            int n = idx >> 8, k = idx & 255;
            float c = expf(ls[n * 257 + k] - Ms[n].x) * Ms[n].y;
            ls[n * 257 + k] = c;
            if (it == 2) extra[(size_t)(b * 16 + n) * HWC + blk * 256 + k] = c;
        }
        __syncthreads();
        for (int c = w; c < 64; c += 8) {
            const float* sp = sr + (size_t)(b * 64 + c) * HWC + blk * 256;
            float a[16];
#pragma unroll
            for (int n = 0; n < 16; n++) a[n] = 0.f;
#pragma unroll
            for (int kk = 0; kk < 8; kk++) {
                int k = lane + kk * 32;
                float s = sp[k];
#pragma unroll
                for (int n = 0; n < 16; n++) a[n] = fmaf(s, ls[n * 257 + k], a[n]);
            }
#pragma unroll
            for (int n = 0; n < 16; n++) {
                float r = wred(a[n]);
                if (lane == 0) atomicAdd(&g_v[(b * 16 + n) * 64 + c], r);
            }
        }
        gbar(2 + 3 * it);

        // ---- C ----
        if (blk < 16) {
            int n = blk, bn = b * 16 + n, c = tid;
            float op = 0.f;
            if (tid < 64) ls[tid] = g_v[bn * 64 + tid];
            __syncthreads();
            if (tid < 64) {
                const float* wr = ww + (size_t)(n * 64 + c) * 64;
                float a = 0.f;
#pragma unroll 8
                for (int cp = 0; cp < 64; cp++) a = fmaf(wr[cp], ls[cp], a);
                op = a + wb[n * 64 + c];
                g_op[bn * 64 + c] = op;
            }
            __syncthreads();
            if (it < 2) {
                if (tid < 64) ls[64 + c] = op * op;
                __syncthreads();
                if (tid == 0) {
                    float s = 0.f;
                    for (int i = 0; i < 64; i++) s += ls[64 + i];
                    ls[128] = fmaxf(sqrtf(s), 1e-12f);
                }
                __syncthreads();
                if (tid < 64) ls[192 + c] = op / ls[128];
                __syncthreads();
                if (tid < 64) {
                    float u = 0.f;
                    for (int cp = 0; cp < 64; cp++) u = fmaf(ww[(size_t)(n * 64 + cp) * 64 + c], ls[192 + cp], u);
                    g_u[bn * 64 + c] = u;
                    g_v[bn * 64 + c] = 0.f;
                }
            } else {
                if (tid < 64) {
                    float t1 = g_T1[b * 64 + c], t2 = g_T2[b * 64 + c];
                    float s1 = t1 + 9216.f * op;
                    float s2 = t2 + 2.f * op * t1 + 9216.f * op * op;
                    s1 += __shfl_xor_sync(0xffffffffu, s1, 1); s1 += __shfl_xor_sync(0xffffffffu, s1, 2);
                    s2 += __shfl_xor_sync(0xffffffffu, s2, 1); s2 += __shfl_xor_sync(0xffffffffu, s2, 2);
                    float mu  = s1 * (1.f / 36864.f);
                    float var = s2 * (1.f / 36864.f) - mu * mu;
                    float inv = rsqrtf(var + EPSN);
                    g_A1[bn * 64 + c] = g1g[c] * inv;
                    g_D1[bn * 64 + c] = (op - mu) * inv * g1g[c] + g1b[c];
                    g_gn2s[bn * 64 + c] = 0.f; g_gn2q[bn * 64 + c] = 0.f;
                }
            }
        }
        if (it < 2) gbar(3 + 3 * it);
    }
}

// ---------------- 5: fused GN1+ReLU+conv3x3(64->64) via mma fp16 ----------------
// Fill: row-segment order — warp w handles (ch_local,row); lanes 0..17 load 18
// consecutive fp32, GN1+ReLU, store halves into channel-last slot layout.
__global__ void __launch_bounds__(256, 2) k_conv1(const float* __restrict__ tg,
                                                  const float* __restrict__ c1b) {
    int bn = blockIdx.z, b = bn >> 4;
    int gx0 = blockIdx.x * 16, gy0 = blockIdx.y * 16;
    int tid = threadIdx.x;
    int warp = tid >> 5, lane = tid & 31;
    int gid = lane >> 2, tg4 = lane & 3;
    int mgroup = warp & 1, ngroup = warp >> 1;

    __shared__ __half in_s[324 * 16];
    __shared__ __half w_s[9 * 64 * 16];
    __shared__ float As[64], Ds[64], Bs[64];

    if (tid < 64) { As[tid] = g_A1[bn * 64 + tid]; Ds[tid] = g_D1[bn * 64 + tid]; Bs[tid] = c1b[tid]; }

    float acc[2][8][4];
#pragma unroll
    for (int s = 0; s < 2; s++)
#pragma unroll
        for (int t = 0; t < 8; t++) { acc[s][t][0] = 0.f; acc[s][t][1] = 0.f; acc[s][t][2] = 0.f; acc[s][t][3] = 0.f; }

    int sidx[8];
#pragma unroll
    for (int t = 0; t < 8; t++) {
        int n = ngroup * 64 + t * 8 + gid;
        sidx[t] = (n >> 4) * 18 + (n & 15);
    }

    const float* tgb = tg + (size_t)b * 64 * HWC;
    const uint4* wp4 = (const uint4*)g_wpack;
    int gxl = gx0 + lane - 1;
    bool xok = (lane < 18) && ((unsigned)gxl < 96u);

    for (int cc4 = 0; cc4 < 4; cc4++) {
        int cc = cc4 * 16;
        __syncthreads();
        {
            uint4* ws4 = (uint4*)w_s;
            const uint4* src = wp4 + cc4 * 1152;
#pragma unroll
            for (int i = 0; i < 4; i++) ws4[tid + i * 256] = src[tid + i * 256];
            int idx = tid + 1024;
            if (idx < 1152) ws4[idx] = src[idx];
        }
        // input fill: 288 (ch,row) segments, coalesced row loads
        for (int seg = warp; seg < 288; seg += 8) {
            int cl = seg / 18, row = seg - cl * 18;
            int ch = cc + cl;
            int gy = gy0 + row - 1;
            float v = 0.f;
            if (xok && (unsigned)gy < 96u) {
                float t0 = tgb[(size_t)ch * HWC + gy * 96 + gxl];
                v = fmaxf(fmaf(t0, As[ch], Ds[ch]), 0.f);
            }
            if (lane < 18)
                in_s[(row * 18 + lane) * 16 + slot_of(cl)] = __float2half_rn(v);
        }
        __syncthreads();
#pragma unroll
        for (int ks = 0; ks < 9; ks++) {
            int toff = (ks / 3) * 18 + (ks % 3);
            uint2 afr[2][2];
#pragma unroll
            for (int s = 0; s < 2; s++) {
                int co_r0 = mgroup * 32 + s * 16 + gid;
                afr[s][0] = *(const uint2*)(w_s + (ks * 64 + co_r0) * 16 + tg4 * 4);
                afr[s][1] = *(const uint2*)(w_s + (ks * 64 + co_r0 + 8) * 16 + tg4 * 4);
            }
#pragma unroll
            for (int t = 0; t < 8; t++) {
                uint2 bb = *(const uint2*)(in_s + (toff + sidx[t]) * 16 + tg4 * 4);
#pragma unroll
                for (int s = 0; s < 2; s++) {
                    asm volatile("mma.sync.aligned.m16n8k16.row.col.f32.f16.f16.f32 "
                                 "{%0,%1,%2,%3}, {%4,%5,%6,%7}, {%8,%9}, {%0,%1,%2,%3};"
                                 : "+f"(acc[s][t][0]), "+f"(acc[s][t][1]),
                                   "+f"(acc[s][t][2]), "+f"(acc[s][t][3])
                                 : "r"(afr[s][0].x), "r"(afr[s][1].x),
                                   "r"(afr[s][0].y), "r"(afr[s][1].y),
                                   "r"(bb.x), "r"(bb.y));
                }
            }
        }
    }

#pragma unroll
    for (int s = 0; s < 2; s++) {
        int co0 = mgroup * 32 + s * 16 + gid;
        int co1 = co0 + 8;
        float b0v = Bs[co0], b1v = Bs[co1];
        float s0 = 0.f, q0 = 0.f, s1 = 0.f, q1 = 0.f;
        __half2* yb0 = (__half2*)(g_y1h + (size_t)(bn * 64 + co0) * HWC);
        __half2* yb1 = (__half2*)(g_y1h + (size_t)(bn * 64 + co1) * HWC);
#pragma unroll
        for (int t = 0; t < 8; t++) {
            int n = ngroup * 64 + t * 8 + tg4 * 2;
            int r = n >> 4, c = n & 15;
            int po = ((gy0 + r) * 96 + gx0 + c) >> 1;
            __half2 h0 = __floats2half2_rn(acc[s][t][0] + b0v, acc[s][t][1] + b0v);
            __half2 h1 = __floats2half2_rn(acc[s][t][2] + b1v, acc[s][t][3] + b1v);
            yb0[po] = h0; yb1[po] = h1;
            float v00 = __low2float(h0), v01 = __high2float(h0);
            float v10 = __low2float(h1), v11 = __high2float(h1);
            s0 += v00 + v01; q0 += v00 * v00 + v01 * v01;
            s1 += v10 + v11; q1 += v10 * v10 + v11 * v11;
        }
        s0 += __shfl_xor_sync(0xffffffffu, s0, 1); s0 += __shfl_xor_sync(0xffffffffu, s0, 2);
        q0 += __shfl_xor_sync(0xffffffffu, q0, 1); q0 += __shfl_xor_sync(0xffffffffu, q0, 2);
        s1 += __shfl_xor_sync(0xffffffffu, s1, 1); s1 += __shfl_xor_sync(0xffffffffu, s1, 2);
        q1 += __shfl_xor_sync(0xffffffffu, q1, 1); q1 += __shfl_xor_sync(0xffffffffu, q1, 2);
        if (tg4 == 0) {
            atomicAdd(&g_gn2s[bn * 64 + co0], s0); atomicAdd(&g_gn2q[bn * 64 + co0], q0);
            atomicAdd(&g_gn2s[bn * 64 + co1], s1); atomicAdd(&g_gn2q[bn * 64 + co1], q1);
        }
    }
}

// ---------------- 7: GN2(inline)+ReLU+conv3x3(64->1) via mma, px on M ----------
__global__ void __launch_bounds__(256) k_conv2(const float* __restrict__ c2b,
                                               const float* __restrict__ g2g,
                                               const float* __restrict__ g2b,
                                               float* __restrict__ msk) {
    int bn = blockIdx.z; int gy0 = blockIdx.y * 16, gx0 = blockIdx.x * 16;
    int tid = threadIdx.x, warp = tid >> 5, lane = tid & 31;
    int gid = lane >> 2, tg4 = lane & 3;
    __shared__ __half in_s[324 * 16];
    __shared__ __half w_s[4608];
    __shared__ float A[64], D[64];
    if (tid < 64) {  // GN2 finalize, redundant per CTA
        float s = g_gn2s[bn * 64 + tid], q = g_gn2q[bn * 64 + tid];
        s += __shfl_xor_sync(0xffffffffu, s, 1); s += __shfl_xor_sync(0xffffffffu, s, 2);
        q += __shfl_xor_sync(0xffffffffu, q, 1); q += __shfl_xor_sync(0xffffffffu, q, 2);
        float mu = s * (1.f / 36864.f), var = q * (1.f / 36864.f) - mu * mu;
        float inv = rsqrtf(var + EPSN);
        A[tid] = g2g[tid] * inv;
        D[tid] = g2b[tid] - mu * inv * g2g[tid];
    }
    {   // conv2 weight pack copy (576 uint4)
        uint4* d = (uint4*)w_s; const uint4* srcw = (const uint4*)g_w2pack;
        for (int i = tid; i < 576; i += 256) d[i] = srcw[i];
    }

    float acc[2][4];
#pragma unroll
    for (int t = 0; t < 2; t++) { acc[t][0] = 0.f; acc[t][1] = 0.f; acc[t][2] = 0.f; acc[t][3] = 0.f; }
    int s0i[2], s1i[2];
#pragma unroll
    for (int t = 0; t < 2; t++) {
        int p0 = (warp * 2 + t) * 16 + gid, p1 = p0 + 8;
        s0i[t] = (p0 >> 4) * 18 + (p0 & 15);
        s1i[t] = (p1 >> 4) * 18 + (p1 & 15);
    }
    const __half* y = g_y1h + (size_t)bn * 64 * HWC;
    int gxl = gx0 + lane - 1;
    bool xok = (lane < 18) && ((unsigned)gxl < 96u);

    for (int cc4 = 0; cc4 < 4; cc4++) {
        int cc = cc4 * 16;
        __syncthreads();
        // input fill: 288 (ch,row) segments, coalesced fp16 row loads
        for (int seg = warp; seg < 288; seg += 8) {
            int cl = seg / 18, row = seg - cl * 18;
            int ch = cc + cl;
            int gy = gy0 + row - 1;
            float v = 0.f;
            if (xok && (unsigned)gy < 96u) {
                float t0 = __half2float(y[(size_t)ch * HWC + gy * 96 + gxl]);
                v = fmaxf(fmaf(t0, A[ch], D[ch]), 0.f);
            }
            if (lane < 18)
                in_s[(row * 18 + lane) * 16 + slot_of(cl)] = __float2half_rn(v);
        }
        __syncthreads();
#pragma unroll
        for (int ks = 0; ks < 9; ks++) {
            int toff = (ks / 3) * 18 + (ks % 3);
            uint2 bb = *(const uint2*)(w_s + ((cc4 * 9 + ks) * 8 + gid) * 16 + tg4 * 4);
#pragma unroll
            for (int t = 0; t < 2; t++) {
                uint2 a01 = *(const uint2*)(in_s + (toff + s0i[t]) * 16 + tg4 * 4);
                uint2 a23 = *(const uint2*)(in_s + (toff + s1i[t]) * 16 + tg4 * 4);
                asm volatile("mma.sync.aligned.m16n8k16.row.col.f32.f16.f16.f32 "
                             "{%0,%1,%2,%3}, {%4,%5,%6,%7}, {%8,%9}, {%0,%1,%2,%3};"
                             : "+f"(acc[t][0]), "+f"(acc[t][1]), "+f"(acc[t][2]), "+f"(acc[t][3])
                             : "r"(a01.x), "r"(a23.x), "r"(a01.y), "r"(a23.y),
                               "r"(bb.x), "r"(bb.y));
            }
        }
    }
    if (tg4 == 0) {
        float bias = c2b[0];
#pragma unroll
        for (int t = 0; t < 2; t++) {
            int p0 = (warp * 2 + t) * 16 + gid, p1 = p0 + 8;
            msk[(size_t)bn * HWC + (gy0 + (p0 >> 4)) * 96 + gx0 + (p0 & 15)] = acc[t][0] + bias;
            msk[(size_t)bn * HWC + (gy0 + (p1 >> 4)) * 96 + gx0 + (p1 & 15)] = acc[t][2] + bias;
        }
    }
}

// ---------------- 8: softmax of msk + center loss + IN1 stats (single pass) ------
__global__ void k_msk_stats(const float* __restrict__ msk, float* __restrict__ out_loss) {
    int bn = blockIdx.x; int t = threadIdx.x;
    const float* m = msk + (size_t)bn * HWC;
    __shared__ float red[256];
    float mx = -1e30f;
    for (int i = t; i < HWC; i += 256) mx = fmaxf(mx, m[i]);
    mx = bmax256(mx, red);
    float se = 0.f, s1 = 0.f, s2 = 0.f;
    float ey = 0.f, ex = 0.f, ey2 = 0.f, ex2 = 0.f;
    const float st = 2.f / 95.f;
    for (int i = t; i < HWC; i += 256) {
        float v = m[i];
        float e = expf(v - mx);
        se += e; s1 += v; s2 += v * v;
        int ii = i / 96, jj = i - ii * 96;
        float yv = -1.f + st * ii, xv = -1.f + st * jj;
        ey += e * yv; ex += e * xv; ey2 += e * yv * yv; ex2 += e * xv * xv;
    }
    se = bsum256(se, red); s1 = bsum256(s1, red); s2 = bsum256(s2, red);
    ey = bsum256(ey, red); ex = bsum256(ex, red);
    ey2 = bsum256(ey2, red); ex2 = bsum256(ex2, red);
    if (t == 0) {
        float inv_se = 1.f / se;
        ey *= inv_se; ex *= inv_se; ey2 *= inv_se; ex2 *= inv_se;
        float lp = ey2 - ey * ey + ex2 - ex * ex;
        atomicAdd(out_loss, lp * (1.f / 128.f));
        float mu = s1 / 9216.f; float var = s2 / 9216.f - mu * mu;
        g_mstat[2 * bn] = mu; g_mstat[2 * bn + 1] = rsqrtf(var + EPSN);
        g_in2s[bn] = 0.f; g_in2q[bn] = 0.f;
    }
}

// ---------------- 10: IN1+ReLU+1x1(16->16) + IN2 stats ----------------
__global__ void k_gen1(const float* __restrict__ msk, const float* __restrict__ in1g,
                       const float* __restrict__ in1b, const float* __restrict__ c3w,
                       const float* __restrict__ c3b) {
    int b = blockIdx.y; int hw = blockIdx.x * 256 + threadIdx.x;
    int t = threadIdx.x;
    __shared__ float w3[256], b3[16], mus[16], invs[16], g1[16], bb1[16];
    __shared__ float bs_[16], bq_[16];
    if (t < 256) w3[t] = c3w[t];
    if (t < 16) {
        b3[t] = c3b[t]; int bn = b * 16 + t;
        mus[t] = g_mstat[2 * bn]; invs[t] = g_mstat[2 * bn + 1];
        g1[t] = in1g[t]; bb1[t] = in1b[t]; bs_[t] = 0.f; bq_[t] = 0.f;
    }
    __syncthreads();
    float r[16];
#pragma unroll
    for (int n = 0; n < 16; n++) {
        float m = msk[(size_t)(b * 16 + n) * HWC + hw];
        r[n] = fmaxf((m - mus[n]) * invs[n] * g1[n] + bb1[n], 0.f);
    }
#pragma unroll
    for (int o = 0; o < 16; o++) {
        float a = b3[o];
#pragma unroll
        for (int n = 0; n < 16; n++) a = fmaf(w3[o * 16 + n], r[n], a);
        g_g2[(size_t)(b * 16 + o) * HWC + hw] = a;
        float s = wred(a), q = wred(a * a);
        if ((t & 31) == 0) { atomicAdd(&bs_[o], s); atomicAdd(&bq_[o], q); }
    }
    __syncthreads();
    if (t < 16) { atomicAdd(&g_in2s[b * 16 + t], bs_[t]); atomicAdd(&g_in2q[b * 16 + t], bq_[t]); }
}

// ---------------- 12: IN2+ReLU+1x1(16->3)+sigmoid -> rec (IN2 stats inline) ------
__global__ void k_rec(const float* __restrict__ in2g, const float* __restrict__ in2b,
                      const float* __restrict__ c4w, const float* __restrict__ c4b,
                      float* __restrict__ out) {
    int b = blockIdx.y; int hw = blockIdx.x * 256 + threadIdx.x; int t = threadIdx.x;
    __shared__ float w4[48], mus[16], invs[16], g2[16], bb2[16];
    if (t < 48) w4[t] = c4w[t];
    if (t < 16) {
        int bo = b * 16 + t;
        float mu = g_in2s[bo] * (1.f / 9216.f);
        float var = g_in2q[bo] * (1.f / 9216.f) - mu * mu;
        mus[t] = mu; invs[t] = rsqrtf(var + EPSN);
        g2[t] = in2g[t]; bb2[t] = in2b[t];
    }
    __syncthreads();
    float x[16];
#pragma unroll
    for (int o = 0; o < 16; o++) {
        float v = g_g2[(size_t)(b * 16 + o) * HWC + hw];
        x[o] = fmaxf((v - mus[o]) * invs[o] * g2[o] + bb2[o], 0.f);
    }
#pragma unroll
    for (int o2 = 0; o2 < 3; o2++) {
        float a = c4b[o2];
#pragma unroll
        for (int o = 0; o < 16; o++) a = fmaf(w4[o2 * 16 + o], x[o], a);
        out[(size_t)(b * 3 + o2) * HWC + hw] = 1.f / (1.f + expf(-a));
    }
}

// ---------------- 13: op_out = op[bnc] * msk[bn,hw] (float4) ----------------
__global__ void k_opout(const float* __restrict__ msk, float* __restrict__ out) {
    int bn = blockIdx.y; int i4 = blockIdx.x * 256 + threadIdx.x;   // 0..2303
    __shared__ float ops[64];
    if (threadIdx.x < 64) ops[threadIdx.x] = g_op[bn * 64 + threadIdx.x];
    __syncthreads();
    float4 m4 = ((const float4*)(msk + (size_t)bn * HWC))[i4];
    float* ob = out + (size_t)bn * 64 * HWC;
#pragma unroll 8
    for (int c = 0; c < 64; c++) {
        float s = ops[c];
        float4 r; r.x = s * m4.x; r.y = s * m4.y; r.z = s * m4.z; r.w = s * m4.w;
        ((float4*)(ob + (size_t)c * HWC))[i4] = r;
    }
}

// ---------------- launch ----------------
extern "C" void kernel_launch(void* const* d_in, const int* in_sizes, int n_in,
                              void* d_out, int out_size) {
    const float* sr   = (const float*)d_in[0];
    const float* tg   = (const float*)d_in[1];
    const float* ww   = (const float*)d_in[2];
    const float* wb   = (const float*)d_in[3];
    const float* gn1g = (const float*)d_in[4];
    const float* gn1b = (const float*)d_in[5];
    const float* c1w  = (const float*)d_in[6];
    const float* c1b  = (const float*)d_in[7];
    const float* gn2g = (const float*)d_in[8];
    const float* gn2b = (const float*)d_in[9];
    const float* c2w  = (const float*)d_in[10];
    const float* c2b  = (const float*)d_in[11];
    const float* in1g = (const float*)d_in[12];
    const float* in1b = (const float*)d_in[13];
    const float* c3w  = (const float*)d_in[14];
    const float* c3b  = (const float*)d_in[15];
    const float* in2g = (const float*)d_in[16];
    const float* in2b = (const float*)d_in[17];
    const float* c4w  = (const float*)d_in[18];
    const float* c4b  = (const float*)d_in[19];
    float* out = (float*)d_out;
    float* out_msk  = out + 75497472;
    float* out_rec  = out + 76677120;
    float* out_loss = out + 76898304;
    float* out_cof  = out + 76898305;

    k_colsum<<<656, 256>>>(sr, tg, c1w, c2w, out_loss);
    k_route<<<dim3(36, 8), 256>>>(sr, ww, wb, gn1g, gn1b, out_cof);
    k_conv1<<<dim3(6, 6, 128), 256>>>(tg, c1b);
    k_conv2<<<dim3(6, 6, 128), 256>>>(c2b, gn2g, gn2b, out_msk);
    k_msk_stats<<<128, 256>>>(out_msk, out_loss);
    k_gen1<<<dim3(36, 8), 256>>>(out_msk, in1g, in1b, c3w, c3b);
    k_rec<<<dim3(36, 8), 256>>>(in2g, in2b, c4w, c4b, out_rec);
    k_opout<<<dim3(9, 128), 256>>>(out_msk, out);
}

// round 15
// speedup vs baseline: 2.2527x; 2.2527x over previous
#include <cuda_runtime.h>
#include <cuda_fp16.h>
#include <cstdint>
#include <cstddef>

#define HWC 9216
#define EPSN 1e-5f

// ---------------- scratch (__device__ globals; no allocation) ----------------
// y1 packed conv2-native: [bn][chunk4][px 9216][16 cin-slots] fp16
__device__ __align__(16) __half g_y1p[75497472];
__device__ float g_g2[1179648];       // gen-block intermediate [8,16,9216]
__device__ float g_tsum[512];         // sum_hw sr [8,64]
__device__ float g_T1[512];           // sum_hw tg
__device__ float g_T2[512];           // sum_hw tg^2
__device__ float g_op[8192];          // [128,64]
__device__ float g_u[8192];           // W^T opn
__device__ float g_v[8192];           // sum_hw sr*cof
__device__ float g_A1[8192];          // GN1 affine scale
__device__ float g_D1[8192];          // GN1 affine shift
__device__ float g_gn2s[8192];
__device__ float g_gn2q[8192];
__device__ float g_mstat[256];        // per-bn (mu, invstd) of msk
__device__ float g_in2s[128];
__device__ float g_in2q[128];
__device__ float2 g_pms[4608];        // per-(bn,blk) online softmax partials (m,s)
__device__ unsigned g_barc[16];       // grid-barrier counters
__device__ __align__(16) __half g_wpack[36864];   // packed fp16 conv1 weights
__device__ __align__(16) __half g_w2pack[4608];   // conv2 weights: [chunk4][tap9][n8][slot16]

// ---------------- helpers ----------------
__device__ __forceinline__ float wred(float v) {
#pragma unroll
    for (int o = 16; o > 0; o >>= 1) v += __shfl_xor_sync(0xffffffffu, v, o);
    return v;
}
__device__ __forceinline__ float bsum256(float v, float* red) {
    int t = threadIdx.x; red[t] = v; __syncthreads();
#pragma unroll
    for (int s = 128; s > 0; s >>= 1) { if (t < s) red[t] += red[t + s]; __syncthreads(); }
    float r = red[0]; __syncthreads(); return r;
}
__device__ __forceinline__ float bmax256(float v, float* red) {
    int t = threadIdx.x; red[t] = v; __syncthreads();
#pragma unroll
    for (int s = 128; s > 0; s >>= 1) { if (t < s) red[t] = fmaxf(red[t], red[t + s]); __syncthreads(); }
    float r = red[0]; __syncthreads(); return r;
}
// grid barrier: all 288 CTAs of k_route arrive. Residency guaranteed by occupancy.
__device__ __forceinline__ void gbar(int id) {
    __syncthreads();
    if (threadIdx.x == 0) {
        __threadfence();
        atomicAdd(&g_barc[id], 1u);
        while (*(volatile unsigned*)&g_barc[id] < 288u) __nanosleep(64);
        __threadfence();
    }
    __syncthreads();
}

// ---------------- 1: colsum (blocks 0..511) + weight packs + barrier reset -------
__global__ void k_colsum(const float* __restrict__ sr, const float* __restrict__ tg,
                         const float* __restrict__ c1w, const float* __restrict__ c2w,
                         float* __restrict__ out_loss) {
    if (blockIdx.x >= 512) {
        int idx = (blockIdx.x - 512) * 256 + threadIdx.x;   // 0..36863
        if (idx == 0) out_loss[0] = 0.f;
        if (idx < 16) g_barc[idx] = 0u;
        {   // conv1 weights
            int slot = idx & 15;
            int co = (idx >> 4) & 63;
            int rest = idx >> 10;
            int tap = rest % 9, chunk = rest / 9;
            int p = slot >> 2, pos = slot & 3;
            int cin = 2 * p + (pos & 1) + ((pos >> 1) << 3);
            g_wpack[idx] = __float2half_rn(c1w[(size_t)(co * 64 + chunk * 16 + cin) * 9 + tap]);
        }
        if (idx < 4608) {   // conv2 weights, B-fragment layout, n=0 real / n>0 zero
            int slot = idx & 15;
            int n = (idx >> 4) & 7;
            int rest = idx >> 7;               // chunk*9 + tap
            int tap = rest % 9, chunk = rest / 9;
            int p = slot >> 2, pos = slot & 3;
            int cin = 2 * p + (pos & 1) + ((pos >> 1) << 3);
            float wv = (n == 0) ? c2w[(chunk * 16 + cin) * 9 + tap] : 0.f;
            g_w2pack[idx] = __float2half_rn(wv);
        }
        return;
    }
    int bc = blockIdx.x;
    const float4* ps = (const float4*)(sr + (size_t)bc * HWC);
    const float4* pt = (const float4*)(tg + (size_t)bc * HWC);
    float s0 = 0.f, s1 = 0.f, s2 = 0.f;
    for (int i = threadIdx.x; i < 2304; i += 256) {
        float4 a = ps[i], b = pt[i];
        s0 += a.x + a.y + a.z + a.w;
        s1 += b.x + b.y + b.z + b.w;
        s2 += b.x * b.x + b.y * b.y + b.z * b.z + b.w * b.w;
    }
    __shared__ float red[256];
    s0 = bsum256(s0, red); s1 = bsum256(s1, red); s2 = bsum256(s2, red);
    if (threadIdx.x == 0) { g_tsum[bc] = s0; g_T1[bc] = s1; g_T2[bc] = s2; }
}

// ---------------- 2: fused dynamic-routing loop (persistent, grid barriers) ------
__global__ void __launch_bounds__(256, 2) k_route(
    const float* __restrict__ sr, const float* __restrict__ ww,
    const float* __restrict__ wb, const float* __restrict__ g1g,
    const float* __restrict__ g1b, float* __restrict__ extra)
{
    __shared__ float us[1024];
    __shared__ float ls[16 * 257];
    __shared__ float2 Ms[16];
    int b = blockIdx.y, blk = blockIdx.x;
    int tid = threadIdx.x;
    int hw = blk * 256 + tid;
    int w = tid >> 5, lane = tid & 31;

    // ---- C0 ----
    if (blk < 16) {
        int n = blk, bn = b * 16 + n, c = tid;
        float op = 0.f;
        if (tid < 64) ls[tid] = g_tsum[b * 64 + tid];
        __syncthreads();
        if (tid < 64) {
            const float* wr = ww + (size_t)(n * 64 + c) * 64;
            float a = 0.f;
#pragma unroll 8
            for (int cp = 0; cp < 64; cp++) a = fmaf(wr[cp], ls[cp], a);
            op = a + wb[n * 64 + c] * 9216.f;
            g_op[bn * 64 + c] = op;
            ls[64 + c] = op * op;
        }
        __syncthreads();
        if (tid == 0) {
            float s = 0.f;
            for (int i = 0; i < 64; i++) s += ls[64 + i];
            ls[128] = fmaxf(sqrtf(s), 1e-12f);
        }
        __syncthreads();
        if (tid < 64) ls[192 + c] = op / ls[128];
        __syncthreads();
        if (tid < 64) {
            float u = 0.f;
            for (int cp = 0; cp < 64; cp++) u = fmaf(ww[(size_t)(n * 64 + cp) * 64 + c], ls[192 + cp], u);
            g_u[bn * 64 + c] = u;
            g_v[bn * 64 + c] = 0.f;
        }
    }
    gbar(0);

    for (int it = 0; it < 3; it++) {
        // ---- A ----
        __syncthreads();
        for (int i = tid; i < 1024; i += 256) us[i] = g_u[b * 1024 + i];
        __syncthreads();
        float acc[16];
#pragma unroll
        for (int n = 0; n < 16; n++) acc[n] = 0.f;
        {
            const float* sp = sr + (size_t)b * 64 * HWC + hw;
            for (int c = 0; c < 64; c++) {
                float v = sp[(size_t)c * HWC];
#pragma unroll
                for (int n = 0; n < 16; n++) acc[n] = fmaf(us[n * 64 + c], v, acc[n]);
            }
        }
#pragma unroll
        for (int n = 0; n < 16; n++) ls[n * 257 + tid] = acc[n];
        __syncthreads();
#pragma unroll
        for (int nn = 0; nn < 2; nn++) {
            int n = w * 2 + nn;
            float v[8]; float mx = -1e30f;
#pragma unroll
            for (int j = 0; j < 8; j++) { v[j] = ls[n * 257 + lane + 32 * j]; mx = fmaxf(mx, v[j]); }
#pragma unroll
            for (int o = 16; o > 0; o >>= 1) mx = fmaxf(mx, __shfl_xor_sync(0xffffffffu, mx, o));
            float s = 0.f;
#pragma unroll
            for (int j = 0; j < 8; j++) s += expf(v[j] - mx);
            s = wred(s);
            if (lane == 0) g_pms[(b * 16 + n) * 36 + blk] = make_float2(mx, s);
        }
        gbar(1 + 3 * it);

        // ---- B ----
        if (tid < 16) {
            const float2* pp = g_pms + (b * 16 + tid) * 36;
            float M = -1e30f;
#pragma unroll
            for (int i = 0; i < 36; i++) M = fmaxf(M, pp[i].x);
            float S = 0.f;
#pragma unroll
            for (int i = 0; i < 36; i++) S += pp[i].y * expf(pp[i].x - M);
            Ms[tid] = make_float2(M, 1.f / S);
        }
        __syncthreads();
        for (int idx = tid; idx < 4096; idx += 256) {
            int n = idx >> 8, k = idx & 255;
            float c = expf(ls[n * 257 + k] - Ms[n].x) * Ms[n].y;
            ls[n * 257 + k] = c;
            if (it == 2) extra[(size_t)(b * 16 + n) * HWC + blk * 256 + k] = c;
        }
        __syncthreads();
        for (int c = w; c < 64; c += 8) {
            const float* sp = sr + (size_t)(b * 64 + c) * HWC + blk * 256;
            float a[16];
#pragma unroll
            for (int n = 0; n < 16; n++) a[n] = 0.f;
#pragma unroll
            for (int kk = 0; kk < 8; kk++) {
                int k = lane + kk * 32;
                float s = sp[k];
#pragma unroll
                for (int n = 0; n < 16; n++) a[n] = fmaf(s, ls[n * 257 + k], a[n]);
            }
#pragma unroll
            for (int n = 0; n < 16; n++) {
                float r = wred(a[n]);
                if (lane == 0) atomicAdd(&g_v[(b * 16 + n) * 64 + c], r);
            }
        }
        gbar(2 + 3 * it);

        // ---- C ----
        if (blk < 16) {
            int n = blk, bn = b * 16 + n, c = tid;
            float op = 0.f;
            if (tid < 64) ls[tid] = g_v[bn * 64 + tid];
            __syncthreads();
            if (tid < 64) {
                const float* wr = ww + (size_t)(n * 64 + c) * 64;
                float a = 0.f;
#pragma unroll 8
                for (int cp = 0; cp < 64; cp++) a = fmaf(wr[cp], ls[cp], a);
                op = a + wb[n * 64 + c];
                g_op[bn * 64 + c] = op;
            }
            __syncthreads();
            if (it < 2) {
                if (tid < 64) ls[64 + c] = op * op;
                __syncthreads();
                if (tid == 0) {
                    float s = 0.f;
                    for (int i = 0; i < 64; i++) s += ls[64 + i];
                    ls[128] = fmaxf(sqrtf(s), 1e-12f);
                }
                __syncthreads();
                if (tid < 64) ls[192 + c] = op / ls[128];
                __syncthreads();
                if (tid < 64) {
                    float u = 0.f;
                    for (int cp = 0; cp < 64; cp++) u = fmaf(ww[(size_t)(n * 64 + cp) * 64 + c], ls[192 + cp], u);
                    g_u[bn * 64 + c] = u;
                    g_v[bn * 64 + c] = 0.f;
                }
            } else {
                if (tid < 64) {
                    float t1 = g_T1[b * 64 + c], t2 = g_T2[b * 64 + c];
                    float s1 = t1 + 9216.f * op;
                    float s2 = t2 + 2.f * op * t1 + 9216.f * op * op;
                    s1 += __shfl_xor_sync(0xffffffffu, s1, 1); s1 += __shfl_xor_sync(0xffffffffu, s1, 2);
                    s2 += __shfl_xor_sync(0xffffffffu, s2, 1); s2 += __shfl_xor_sync(0xffffffffu, s2, 2);
                    float mu  = s1 * (1.f / 36864.f);
                    float var = s2 * (1.f / 36864.f) - mu * mu;
                    float inv = rsqrtf(var + EPSN);
                    g_A1[bn * 64 + c] = g1g[c] * inv;
                    g_D1[bn * 64 + c] = (op - mu) * inv * g1g[c] + g1b[c];
                    g_gn2s[bn * 64 + c] = 0.f; g_gn2q[bn * 64 + c] = 0.f;
                }
            }
        }
        if (it < 2) gbar(3 + 3 * it);
    }
}

// ---------------- 5: fused GN1+ReLU+conv3x3(64->64) via mma fp16 (R12 fill) ------
// y1 written in conv2-native packed layout: [bn][chunk][px][slot16] fp16.
__global__ void __launch_bounds__(256, 2) k_conv1(const float* __restrict__ tg,
                                                  const float* __restrict__ c1b) {
    int bn = blockIdx.z, b = bn >> 4;
    int gx0 = blockIdx.x * 16, gy0 = blockIdx.y * 16;
    int tid = threadIdx.x;
    int warp = tid >> 5, lane = tid & 31;
    int gid = lane >> 2, tg4 = lane & 3;
    int mgroup = warp & 1, ngroup = warp >> 1;

    __shared__ __half in_s[324 * 16];
    __shared__ __half w_s[9 * 64 * 16];
    __shared__ float As[64], Ds[64], Bs[64];

    if (tid < 64) { As[tid] = g_A1[bn * 64 + tid]; Ds[tid] = g_D1[bn * 64 + tid]; Bs[tid] = c1b[tid]; }

    float acc[2][8][4];
#pragma unroll
    for (int s = 0; s < 2; s++)
#pragma unroll
        for (int t = 0; t < 8; t++) { acc[s][t][0] = 0.f; acc[s][t][1] = 0.f; acc[s][t][2] = 0.f; acc[s][t][3] = 0.f; }

    int sidx[8];
#pragma unroll
    for (int t = 0; t < 8; t++) {
        int n = ngroup * 64 + t * 8 + gid;
        sidx[t] = (n >> 4) * 18 + (n & 15);
    }

    const float* tgb = tg + (size_t)b * 64 * HWC;
    const uint4* wp4 = (const uint4*)g_wpack;

    for (int cc4 = 0; cc4 < 4; cc4++) {
        int cc = cc4 * 16;
        __syncthreads();
        {
            uint4* ws4 = (uint4*)w_s;
            const uint4* src = wp4 + cc4 * 1152;
#pragma unroll
            for (int i = 0; i < 4; i++) ws4[tid + i * 256] = src[tid + i * 256];
            int idx = tid + 1024;
            if (idx < 1152) ws4[idx] = src[idx];
        }
        // input halo tile: GN1 affine + ReLU -> half2, shift-only indexing (R12)
        for (int idx = tid; idx < 2592; idx += 256) {
            int sp = idx >> 3, j = idx & 7;
            int cin0 = (j & 1) ? (j + 7) : j;
            int rr = sp / 18, c2 = sp - rr * 18;
            int gy = gy0 + rr - 1, gx = gx0 + c2 - 1;
            float v0 = 0.f, v1 = 0.f;
            if ((unsigned)gy < 96u && (unsigned)gx < 96u) {
                int ch0 = cc + cin0;
                size_t base = (size_t)gy * 96 + gx;
                float t0 = tgb[(size_t)ch0 * HWC + base];
                float t1 = tgb[(size_t)(ch0 + 1) * HWC + base];
                v0 = fmaxf(fmaf(t0, As[ch0], Ds[ch0]), 0.f);
                v1 = fmaxf(fmaf(t1, As[ch0 + 1], Ds[ch0 + 1]), 0.f);
            }
            ((__half2*)in_s)[sp * 8 + j] = __floats2half2_rn(v0, v1);
        }
        __syncthreads();
#pragma unroll
        for (int ks = 0; ks < 9; ks++) {
            int toff = (ks / 3) * 18 + (ks % 3);
            uint2 afr[2][2];
#pragma unroll
            for (int s = 0; s < 2; s++) {
                int co_r0 = mgroup * 32 + s * 16 + gid;
                afr[s][0] = *(const uint2*)(w_s + (ks * 64 + co_r0) * 16 + tg4 * 4);
                afr[s][1] = *(const uint2*)(w_s + (ks * 64 + co_r0 + 8) * 16 + tg4 * 4);
            }
#pragma unroll
            for (int t = 0; t < 8; t++) {
                uint2 bb = *(const uint2*)(in_s + (toff + sidx[t]) * 16 + tg4 * 4);
#pragma unroll
                for (int s = 0; s < 2; s++) {
                    asm volatile("mma.sync.aligned.m16n8k16.row.col.f32.f16.f16.f32 "
                                 "{%0,%1,%2,%3}, {%4,%5,%6,%7}, {%8,%9}, {%0,%1,%2,%3};"
                                 : "+f"(acc[s][t][0]), "+f"(acc[s][t][1]),
                                   "+f"(acc[s][t][2]), "+f"(acc[s][t][3])
                                 : "r"(afr[s][0].x), "r"(afr[s][1].x),
                                   "r"(afr[s][0].y), "r"(afr[s][1].y),
                                   "r"(bb.x), "r"(bb.y));
                }
            }
        }
    }

    // epilogue: bias; packed fp16 store of y1; GN2 stats from the ROUNDED values
#pragma unroll
    for (int s = 0; s < 2; s++) {
        int co0 = mgroup * 32 + s * 16 + gid;
        int co1 = co0 + 8;
        int chunkb = mgroup * 2 + s;               // co0>>4
        int sl0 = 4 * (gid >> 1) + (gid & 1);      // slot_of(gid)
        int sl1 = sl0 + 2;                         // slot_of(gid+8)
        float b0v = Bs[co0], b1v = Bs[co1];
        float s0 = 0.f, q0 = 0.f, s1 = 0.f, q1 = 0.f;
        __half* yb = g_y1p + (size_t)(bn * 4 + chunkb) * HWC * 16;
#pragma unroll
        for (int t = 0; t < 8; t++) {
            int n = ngroup * 64 + t * 8 + tg4 * 2;
            int r = n >> 4, c = n & 15;
            size_t px = (size_t)(gy0 + r) * 96 + gx0 + c;
            __half h00 = __float2half_rn(acc[s][t][0] + b0v);
            __half h01 = __float2half_rn(acc[s][t][1] + b0v);
            __half h10 = __float2half_rn(acc[s][t][2] + b1v);
            __half h11 = __float2half_rn(acc[s][t][3] + b1v);
            yb[px * 16 + sl0] = h00; yb[(px + 1) * 16 + sl0] = h01;
            yb[px * 16 + sl1] = h10; yb[(px + 1) * 16 + sl1] = h11;
            float v00 = __half2float(h00), v01 = __half2float(h01);
            float v10 = __half2float(h10), v11 = __half2float(h11);
            s0 += v00 + v01; q0 += v00 * v00 + v01 * v01;
            s1 += v10 + v11; q1 += v10 * v10 + v11 * v11;
        }
        s0 += __shfl_xor_sync(0xffffffffu, s0, 1); s0 += __shfl_xor_sync(0xffffffffu, s0, 2);
        q0 += __shfl_xor_sync(0xffffffffu, q0, 1); q0 += __shfl_xor_sync(0xffffffffu, q0, 2);
        s1 += __shfl_xor_sync(0xffffffffu, s1, 1); s1 += __shfl_xor_sync(0xffffffffu, s1, 2);
        q1 += __shfl_xor_sync(0xffffffffu, q1, 1); q1 += __shfl_xor_sync(0xffffffffu, q1, 2);
        if (tg4 == 0) {
            atomicAdd(&g_gn2s[bn * 64 + co0], s0); atomicAdd(&g_gn2q[bn * 64 + co0], q0);
            atomicAdd(&g_gn2s[bn * 64 + co1], s1); atomicAdd(&g_gn2q[bn * 64 + co1], q1);
        }
    }
}

// ---------------- 7: GN2(inline)+ReLU+conv3x3(64->1) via mma, px on M ----------
// Fill: predicated uint4 copies from packed y1 + in-register affine/ReLU.
// FIX vs R14: OOB halo pixels store literal zeros (no affine applied).
__global__ void __launch_bounds__(256) k_conv2(const float* __restrict__ c2b,
                                               const float* __restrict__ g2g,
                                               const float* __restrict__ g2b,
                                               float* __restrict__ msk) {
    int bn = blockIdx.z; int gy0 = blockIdx.y * 16, gx0 = blockIdx.x * 16;
    int tid = threadIdx.x, warp = tid >> 5, lane = tid & 31;
    int gid = lane >> 2, tg4 = lane & 3;
    __shared__ __half in_s[324 * 16];
    __shared__ __half w_s[4608];
    __shared__ float A[64], D[64];
    if (tid < 64) {  // GN2 finalize, redundant per CTA
        float s = g_gn2s[bn * 64 + tid], q = g_gn2q[bn * 64 + tid];
        s += __shfl_xor_sync(0xffffffffu, s, 1); s += __shfl_xor_sync(0xffffffffu, s, 2);
        q += __shfl_xor_sync(0xffffffffu, q, 1); q += __shfl_xor_sync(0xffffffffu, q, 2);
        float mu = s * (1.f / 36864.f), var = q * (1.f / 36864.f) - mu * mu;
        float inv = rsqrtf(var + EPSN);
        A[tid] = g2g[tid] * inv;
        D[tid] = g2b[tid] - mu * inv * g2g[tid];
    }
    {   // conv2 weight pack copy (576 uint4)
        uint4* d = (uint4*)w_s; const uint4* srcw = (const uint4*)g_w2pack;
        for (int i = tid; i < 576; i += 256) d[i] = srcw[i];
    }

    float acc[2][4];
#pragma unroll
    for (int t = 0; t < 2; t++) { acc[t][0] = 0.f; acc[t][1] = 0.f; acc[t][2] = 0.f; acc[t][3] = 0.f; }
    int s0i[2], s1i[2];
#pragma unroll
    for (int t = 0; t < 2; t++) {
        int p0 = (warp * 2 + t) * 16 + gid, p1 = p0 + 8;
        s0i[t] = (p0 >> 4) * 18 + (p0 & 15);
        s1i[t] = (p1 >> 4) * 18 + (p1 & 15);
    }
    const uint4* xsrc = (const uint4*)g_y1p;

    for (int cc4 = 0; cc4 < 4; cc4++) {
        __syncthreads();
        // input: 648 predicated uint4 copies + in-register GN2 affine/ReLU
        size_t plane = (size_t)(bn * 4 + cc4) * HWC;
        for (int idx = tid; idx < 648; idx += 256) {
            int r = idx / 36, q = idx - r * 36;
            int pxr = q >> 1, hs = q & 1;
            int gy = gy0 + r - 1, gx = gx0 + pxr - 1;
            union { uint4 u; __half h[8]; } buf;
            buf.u = make_uint4(0u, 0u, 0u, 0u);
            if ((unsigned)gy < 96u && (unsigned)gx < 96u) {
                buf.u = xsrc[(plane + (size_t)gy * 96 + gx) * 2 + hs];
#pragma unroll
                for (int e = 0; e < 8; e++) {
                    int slot = hs * 8 + e;
                    int p2 = slot >> 2, pos = slot & 3;
                    int cin = 2 * p2 + (pos & 1) + ((pos >> 1) << 3);
                    int ch = cc4 * 16 + cin;
                    float vv = fmaxf(fmaf(__half2float(buf.h[e]), A[ch], D[ch]), 0.f);
                    buf.h[e] = __float2half_rn(vv);
                }
            }
            ((uint4*)in_s)[(r * 18 + pxr) * 2 + hs] = buf.u;
        }
        __syncthreads();
#pragma unroll
        for (int ks = 0; ks < 9; ks++) {
            int toff = (ks / 3) * 18 + (ks % 3);
            uint2 bb = *(const uint2*)(w_s + ((cc4 * 9 + ks) * 8 + gid) * 16 + tg4 * 4);
#pragma unroll
            for (int t = 0; t < 2; t++) {
                uint2 a01 = *(const uint2*)(in_s + (toff + s0i[t]) * 16 + tg4 * 4);
                uint2 a23 = *(const uint2*)(in_s + (toff + s1i[t]) * 16 + tg4 * 4);
                asm volatile("mma.sync.aligned.m16n8k16.row.col.f32.f16.f16.f32 "
                             "{%0,%1,%2,%3}, {%4,%5,%6,%7}, {%8,%9}, {%0,%1,%2,%3};"
                             : "+f"(acc[t][0]), "+f"(acc[t][1]), "+f"(acc[t][2]), "+f"(acc[t][3])
                             : "r"(a01.x), "r"(a23.x), "r"(a01.y), "r"(a23.y),
                               "r"(bb.x), "r"(bb.y));
            }
        }
    }
    if (tg4 == 0) {
        float bias = c2b[0];
#pragma unroll
        for (int t = 0; t < 2; t++) {
            int p0 = (warp * 2 + t) * 16 + gid, p1 = p0 + 8;
            msk[(size_t)bn * HWC + (gy0 + (p0 >> 4)) * 96 + gx0 + (p0 & 15)] = acc[t][0] + bias;
            msk[(size_t)bn * HWC + (gy0 + (p1 >> 4)) * 96 + gx0 + (p1 & 15)] = acc[t][2] + bias;
        }
    }
}

// ---------------- 8: softmax of msk + center loss + IN1 stats (single pass) ------
__global__ void k_msk_stats(const float* __restrict__ msk, float* __restrict__ out_loss) {
    int bn = blockIdx.x; int t = threadIdx.x;
    const float* m = msk + (size_t)bn * HWC;
    __shared__ float red[256];
    float mx = -1e30f;
    for (int i = t; i < HWC; i += 256) mx = fmaxf(mx, m[i]);
    mx = bmax256(mx, red);
    float se = 0.f, s1 = 0.f, s2 = 0.f;
    float ey = 0.f, ex = 0.f, ey2 = 0.f, ex2 = 0.f;
    const float st = 2.f / 95.f;
    for (int i = t; i < HWC; i += 256) {
        float v = m[i];
        float e = expf(v - mx);
        se += e; s1 += v; s2 += v * v;
        int ii = i / 96, jj = i - ii * 96;
        float yv = -1.f + st * ii, xv = -1.f + st * jj;
        ey += e * yv; ex += e * xv; ey2 += e * yv * yv; ex2 += e * xv * xv;
    }
    se = bsum256(se, red); s1 = bsum256(s1, red); s2 = bsum256(s2, red);
    ey = bsum256(ey, red); ex = bsum256(ex, red);
    ey2 = bsum256(ey2, red); ex2 = bsum256(ex2, red);
    if (t == 0) {
        float inv_se = 1.f / se;
        ey *= inv_se; ex *= inv_se; ey2 *= inv_se; ex2 *= inv_se;
        float lp = ey2 - ey * ey + ex2 - ex * ex;
        atomicAdd(out_loss, lp * (1.f / 128.f));
        float mu = s1 / 9216.f; float var = s2 / 9216.f - mu * mu;
        g_mstat[2 * bn] = mu; g_mstat[2 * bn + 1] = rsqrtf(var + EPSN);
        g_in2s[bn] = 0.f; g_in2q[bn] = 0.f;
    }
}

// ---------------- 10: IN1+ReLU+1x1(16->16) + IN2 stats ----------------
__global__ void k_gen1(const float* __restrict__ msk, const float* __restrict__ in1g,
                       const float* __restrict__ in1b, const float* __restrict__ c3w,
                       const float* __restrict__ c3b) {
    int b = blockIdx.y; int hw = blockIdx.x * 256 + threadIdx.x;
    int t = threadIdx.x;
    __shared__ float w3[256], b3[16], mus[16], invs[16], g1[16], bb1[16];
    __shared__ float bs_[16], bq_[16];
    if (t < 256) w3[t] = c3w[t];
    if (t < 16) {
        b3[t] = c3b[t]; int bn = b * 16 + t;
        mus[t] = g_mstat[2 * bn]; invs[t] = g_mstat[2 * bn + 1];
        g1[t] = in1g[t]; bb1[t] = in1b[t]; bs_[t] = 0.f; bq_[t] = 0.f;
    }
    __syncthreads();
    float r[16];
#pragma unroll
    for (int n = 0; n < 16; n++) {
        float m = msk[(size_t)(b * 16 + n) * HWC + hw];
        r[n] = fmaxf((m - mus[n]) * invs[n] * g1[n] + bb1[n], 0.f);
    }
#pragma unroll
    for (int o = 0; o < 16; o++) {
        float a = b3[o];
#pragma unroll
        for (int n = 0; n < 16; n++) a = fmaf(w3[o * 16 + n], r[n], a);
        g_g2[(size_t)(b * 16 + o) * HWC + hw] = a;
        float s = wred(a), q = wred(a * a);
        if ((t & 31) == 0) { atomicAdd(&bs_[o], s); atomicAdd(&bq_[o], q); }
    }
    __syncthreads();
    if (t < 16) { atomicAdd(&g_in2s[b * 16 + t], bs_[t]); atomicAdd(&g_in2q[b * 16 + t], bq_[t]); }
}

// ---------------- 12: IN2+ReLU+1x1(16->3)+sigmoid -> rec (IN2 stats inline) ------
__global__ void k_rec(const float* __restrict__ in2g, const float* __restrict__ in2b,
                      const float* __restrict__ c4w, const float* __restrict__ c4b,
                      float* __restrict__ out) {
    int b = blockIdx.y; int hw = blockIdx.x * 256 + threadIdx.x; int t = threadIdx.x;
    __shared__ float w4[48], mus[16], invs[16], g2[16], bb2[16];
    if (t < 48) w4[t] = c4w[t];
    if (t < 16) {
        int bo = b * 16 + t;
        float mu = g_in2s[bo] * (1.f / 9216.f);
        float var = g_in2q[bo] * (1.f / 9216.f) - mu * mu;
        mus[t] = mu; invs[t] = rsqrtf(var + EPSN);
        g2[t] = in2g[t]; bb2[t] = in2b[t];
    }
    __syncthreads();
    float x[16];
#pragma unroll
    for (int o = 0; o < 16; o++) {
        float v = g_g2[(size_t)(b * 16 + o) * HWC + hw];
        x[o] = fmaxf((v - mus[o]) * invs[o] * g2[o] + bb2[o], 0.f);
    }
#pragma unroll
    for (int o2 = 0; o2 < 3; o2++) {
        float a = c4b[o2];
#pragma unroll
        for (int o = 0; o < 16; o++) a = fmaf(w4[o2 * 16 + o], x[o], a);
        out[(size_t)(b * 3 + o2) * HWC + hw] = 1.f / (1.f + expf(-a));
    }
}

// ---------------- 13: op_out = op[bnc] * msk[bn,hw] (float4) ----------------
__global__ void k_opout(const float* __restrict__ msk, float* __restrict__ out) {
    int bn = blockIdx.y; int i4 = blockIdx.x * 256 + threadIdx.x;   // 0..2303
    __shared__ float ops[64];
    if (threadIdx.x < 64) ops[threadIdx.x] = g_op[bn * 64 + threadIdx.x];
    __syncthreads();
    float4 m4 = ((const float4*)(msk + (size_t)bn * HWC))[i4];
    float* ob = out + (size_t)bn * 64 * HWC;
#pragma unroll 8
    for (int c = 0; c < 64; c++) {
        float s = ops[c];
        float4 r; r.x = s * m4.x; r.y = s * m4.y; r.z = s * m4.z; r.w = s * m4.w;
        ((float4*)(ob + (size_t)c * HWC))[i4] = r;
    }
}

// ---------------- launch ----------------
extern "C" void kernel_launch(void* const* d_in, const int* in_sizes, int n_in,
                              void* d_out, int out_size) {
    const float* sr   = (const float*)d_in[0];
    const float* tg   = (const float*)d_in[1];
    const float* ww   = (const float*)d_in[2];
    const float* wb   = (const float*)d_in[3];
    const float* gn1g = (const float*)d_in[4];
    const float* gn1b = (const float*)d_in[5];
    const float* c1w  = (const float*)d_in[6];
    const float* c1b  = (const float*)d_in[7];
    const float* gn2g = (const float*)d_in[8];
    const float* gn2b = (const float*)d_in[9];
    const float* c2w  = (const float*)d_in[10];
    const float* c2b  = (const float*)d_in[11];
    const float* in1g = (const float*)d_in[12];
    const float* in1b = (const float*)d_in[13];
    const float* c3w  = (const float*)d_in[14];
    const float* c3b  = (const float*)d_in[15];
    const float* in2g = (const float*)d_in[16];
    const float* in2b = (const float*)d_in[17];
    const float* c4w  = (const float*)d_in[18];
    const float* c4b  = (const float*)d_in[19];
    float* out = (float*)d_out;
    float* out_msk  = out + 75497472;
    float* out_rec  = out + 76677120;
    float* out_loss = out + 76898304;
    float* out_cof  = out + 76898305;

    k_colsum<<<656, 256>>>(sr, tg, c1w, c2w, out_loss);
    k_route<<<dim3(36, 8), 256>>>(sr, ww, wb, gn1g, gn1b, out_cof);
    k_conv1<<<dim3(6, 6, 128), 256>>>(tg, c1b);
    k_conv2<<<dim3(6, 6, 128), 256>>>(c2b, gn2g, gn2b, out_msk);
    k_msk_stats<<<128, 256>>>(out_msk, out_loss);
    k_gen1<<<dim3(36, 8), 256>>>(out_msk, in1g, in1b, c3w, c3b);
    k_rec<<<dim3(36, 8), 256>>>(in2g, in2b, c4w, c4b, out_rec);
    k_opout<<<dim3(9, 128), 256>>>(out_msk, out);
}

// round 16
// speedup vs baseline: 2.4455x; 1.0856x over previous
#include <cuda_runtime.h>
#include <cuda_fp16.h>
#include <cstdint>
#include <cstddef>

#define HWC 9216
#define EPSN 1e-5f

// ---------------- scratch (__device__ globals; no allocation) ----------------
__device__ __align__(16) __half g_y1p[75497472]; // y1 packed [bn][chunk4][px][slot16]
__device__ __align__(16) __half g_tgp[4718592];  // tg packed [b][chunk4][px][slot16]
__device__ float g_g2[1179648];       // gen-block intermediate [8,16,9216]
__device__ float g_tsum[512];         // sum_hw sr [8,64]
__device__ float g_T1[512];           // sum_hw tg
__device__ float g_T2[512];           // sum_hw tg^2
__device__ float g_op[8192];          // [128,64]
__device__ float g_u[8192];           // W^T opn
__device__ float g_v[8192];           // sum_hw sr*cof
__device__ float g_A1[8192];          // GN1 affine scale
__device__ float g_D1[8192];          // GN1 affine shift
__device__ float g_gn2s[8192];
__device__ float g_gn2q[8192];
__device__ float g_mstat[256];        // per-bn (mu, invstd) of msk
__device__ float g_in2s[128];
__device__ float g_in2q[128];
__device__ float2 g_pms[4608];        // per-(bn,blk) online softmax partials (m,s)
__device__ unsigned g_barc[16];       // grid-barrier counters
__device__ __align__(16) __half g_wpack[36864];   // packed fp16 conv1 weights
__device__ __align__(16) __half g_w2pack[4608];   // conv2 weights: [chunk4][tap9][n8][slot16]

// ---------------- helpers ----------------
__device__ __forceinline__ float wred(float v) {
#pragma unroll
    for (int o = 16; o > 0; o >>= 1) v += __shfl_xor_sync(0xffffffffu, v, o);
    return v;
}
__device__ __forceinline__ float bsum256(float v, float* red) {
    int t = threadIdx.x; red[t] = v; __syncthreads();
#pragma unroll
    for (int s = 128; s > 0; s >>= 1) { if (t < s) red[t] += red[t + s]; __syncthreads(); }
    float r = red[0]; __syncthreads(); return r;
}
__device__ __forceinline__ float bmax256(float v, float* red) {
    int t = threadIdx.x; red[t] = v; __syncthreads();
#pragma unroll
    for (int s = 128; s > 0; s >>= 1) { if (t < s) red[t] = fmaxf(red[t], red[t + s]); __syncthreads(); }
    float r = red[0]; __syncthreads(); return r;
}
__device__ __forceinline__ int slot_of(int c) {   // cin-slot permutation
    return 4 * ((c & 7) >> 1) + ((((c >> 3) & 1) << 1) | (c & 1));
}
__device__ __forceinline__ int cin_of(int slot) { // inverse permutation
    int p = slot >> 2, pos = slot & 3;
    return 2 * p + (pos & 1) + ((pos >> 1) << 3);
}
// grid barrier: all 288 CTAs of k_route arrive. Residency guaranteed by occupancy.
__device__ __forceinline__ void gbar(int id) {
    __syncthreads();
    if (threadIdx.x == 0) {
        __threadfence();
        atomicAdd(&g_barc[id], 1u);
        while (*(volatile unsigned*)&g_barc[id] < 288u) __nanosleep(64);
        __threadfence();
    }
    __syncthreads();
}

// ---------------- 1: colsum (blocks 0..511) + weight packs + barrier reset -------
__global__ void k_colsum(const float* __restrict__ sr, const float* __restrict__ tg,
                         const float* __restrict__ c1w, const float* __restrict__ c2w,
                         float* __restrict__ out_loss) {
    if (blockIdx.x >= 512) {
        int idx = (blockIdx.x - 512) * 256 + threadIdx.x;   // 0..36863
        if (idx == 0) out_loss[0] = 0.f;
        if (idx < 16) g_barc[idx] = 0u;
        {   // conv1 weights
            int slot = idx & 15;
            int co = (idx >> 4) & 63;
            int rest = idx >> 10;
            int tap = rest % 9, chunk = rest / 9;
            int cin = cin_of(slot);
            g_wpack[idx] = __float2half_rn(c1w[(size_t)(co * 64 + chunk * 16 + cin) * 9 + tap]);
        }
        if (idx < 4608) {   // conv2 weights, B-fragment layout, n=0 real / n>0 zero
            int slot = idx & 15;
            int n = (idx >> 4) & 7;
            int rest = idx >> 7;               // chunk*9 + tap
            int tap = rest % 9, chunk = rest / 9;
            int cin = cin_of(slot);
            float wv = (n == 0) ? c2w[(chunk * 16 + cin) * 9 + tap] : 0.f;
            g_w2pack[idx] = __float2half_rn(wv);
        }
        return;
    }
    int bc = blockIdx.x;
    const float4* ps = (const float4*)(sr + (size_t)bc * HWC);
    const float4* pt = (const float4*)(tg + (size_t)bc * HWC);
    float s0 = 0.f, s1 = 0.f, s2 = 0.f;
    for (int i = threadIdx.x; i < 2304; i += 256) {
        float4 a = ps[i], b = pt[i];
        s0 += a.x + a.y + a.z + a.w;
        s1 += b.x + b.y + b.z + b.w;
        s2 += b.x * b.x + b.y * b.y + b.z * b.z + b.w * b.w;
    }
    __shared__ float red[256];
    s0 = bsum256(s0, red); s1 = bsum256(s1, red); s2 = bsum256(s2, red);
    if (threadIdx.x == 0) { g_tsum[bc] = s0; g_T1[bc] = s1; g_T2[bc] = s2; }
}

// ---------------- 1b: pack tg to fp16 conv-native layout ----------------
__global__ void k_tgpack(const float* __restrict__ tg) {
    int b = blockIdx.y; int px = blockIdx.x * 256 + threadIdx.x;
    const float* tp = tg + (size_t)b * 64 * HWC + px;
#pragma unroll
    for (int chunk = 0; chunk < 4; chunk++) {
        union { uint4 u[2]; __half h[16]; } buf;
#pragma unroll
        for (int cin = 0; cin < 16; cin++)
            buf.h[slot_of(cin)] = __float2half_rn(tp[(size_t)(chunk * 16 + cin) * HWC]);
        uint4* dst = (uint4*)(g_tgp + ((size_t)(b * 4 + chunk) * HWC + px) * 16);
        dst[0] = buf.u[0]; dst[1] = buf.u[1];
    }
}

// ---------------- 2: fused dynamic-routing loop (persistent, grid barriers) ------
__global__ void __launch_bounds__(256, 2) k_route(
    const float* __restrict__ sr, const float* __restrict__ ww,
    const float* __restrict__ wb, const float* __restrict__ g1g,
    const float* __restrict__ g1b, float* __restrict__ extra)
{
    __shared__ float us[1024];
    __shared__ float ls[16 * 257];
    __shared__ float2 Ms[16];
    int b = blockIdx.y, blk = blockIdx.x;
    int tid = threadIdx.x;
    int hw = blk * 256 + tid;
    int w = tid >> 5, lane = tid & 31;

    // ---- C0 ----
    if (blk < 16) {
        int n = blk, bn = b * 16 + n, c = tid;
        float op = 0.f;
        if (tid < 64) ls[tid] = g_tsum[b * 64 + tid];
        __syncthreads();
        if (tid < 64) {
            const float* wr = ww + (size_t)(n * 64 + c) * 64;
            float a = 0.f;
#pragma unroll 8
            for (int cp = 0; cp < 64; cp++) a = fmaf(wr[cp], ls[cp], a);
            op = a + wb[n * 64 + c] * 9216.f;
            g_op[bn * 64 + c] = op;
            ls[64 + c] = op * op;
        }
        __syncthreads();
        if (tid == 0) {
            float s = 0.f;
            for (int i = 0; i < 64; i++) s += ls[64 + i];
            ls[128] = fmaxf(sqrtf(s), 1e-12f);
        }
        __syncthreads();
        if (tid < 64) ls[192 + c] = op / ls[128];
        __syncthreads();
        if (tid < 64) {
            float u = 0.f;
            for (int cp = 0; cp < 64; cp++) u = fmaf(ww[(size_t)(n * 64 + cp) * 64 + c], ls[192 + cp], u);
            g_u[bn * 64 + c] = u;
            g_v[bn * 64 + c] = 0.f;
        }
    }
    gbar(0);

    for (int it = 0; it < 3; it++) {
        // ---- A ----
        __syncthreads();
        for (int i = tid; i < 1024; i += 256) us[i] = g_u[b * 1024 + i];
        __syncthreads();
        float acc[16];
#pragma unroll
        for (int n = 0; n < 16; n++) acc[n] = 0.f;
        {
            const float* sp = sr + (size_t)b * 64 * HWC + hw;
            for (int c = 0; c < 64; c++) {
                float v = sp[(size_t)c * HWC];
#pragma unroll
                for (int n = 0; n < 16; n++) acc[n] = fmaf(us[n * 64 + c], v, acc[n]);
            }
        }
#pragma unroll
        for (int n = 0; n < 16; n++) ls[n * 257 + tid] = acc[n];
        __syncthreads();
#pragma unroll
        for (int nn = 0; nn < 2; nn++) {
            int n = w * 2 + nn;
            float v[8]; float mx = -1e30f;
#pragma unroll
            for (int j = 0; j < 8; j++) { v[j] = ls[n * 257 + lane + 32 * j]; mx = fmaxf(mx, v[j]); }
#pragma unroll
            for (int o = 16; o > 0; o >>= 1) mx = fmaxf(mx, __shfl_xor_sync(0xffffffffu, mx, o));
            float s = 0.f;
#pragma unroll
            for (int j = 0; j < 8; j++) s += expf(v[j] - mx);
            s = wred(s);
            if (lane == 0) g_pms[(b * 16 + n) * 36 + blk] = make_float2(mx, s);
        }
        gbar(1 + 3 * it);

        // ---- B ----
        if (tid < 16) {
            const float2* pp = g_pms + (b * 16 + tid) * 36;
            float M = -1e30f;
#pragma unroll
            for (int i = 0; i < 36; i++) M = fmaxf(M, pp[i].x);
            float S = 0.f;
#pragma unroll
            for (int i = 0; i < 36; i++) S += pp[i].y * expf(pp[i].x - M);
            Ms[tid] = make_float2(M, 1.f / S);
        }
        __syncthreads();
        for (int idx = tid; idx < 4096; idx += 256) {
            int n = idx >> 8, k = idx & 255;
            float c = expf(ls[n * 257 + k] - Ms[n].x) * Ms[n].y;
            ls[n * 257 + k] = c;
            if (it == 2) extra[(size_t)(b * 16 + n) * HWC + blk * 256 + k] = c;
        }
        __syncthreads();
        for (int c = w; c < 64; c += 8) {
            const float* sp = sr + (size_t)(b * 64 + c) * HWC + blk * 256;
            float a[16];
#pragma unroll
            for (int n = 0; n < 16; n++) a[n] = 0.f;
#pragma unroll
            for (int kk = 0; kk < 8; kk++) {
                int k = lane + kk * 32;
                float s = sp[k];
#pragma unroll
                for (int n = 0; n < 16; n++) a[n] = fmaf(s, ls[n * 257 + k], a[n]);
            }
#pragma unroll
            for (int n = 0; n < 16; n++) {
                float r = wred(a[n]);
                if (lane == 0) atomicAdd(&g_v[(b * 16 + n) * 64 + c], r);
            }
        }
        gbar(2 + 3 * it);

        // ---- C ----
        if (blk < 16) {
            int n = blk, bn = b * 16 + n, c = tid;
            float op = 0.f;
            if (tid < 64) ls[tid] = g_v[bn * 64 + tid];
            __syncthreads();
            if (tid < 64) {
                const float* wr = ww + (size_t)(n * 64 + c) * 64;
                float a = 0.f;
#pragma unroll 8
                for (int cp = 0; cp < 64; cp++) a = fmaf(wr[cp], ls[cp], a);
                op = a + wb[n * 64 + c];
                g_op[bn * 64 + c] = op;
            }
            __syncthreads();
            if (it < 2) {
                if (tid < 64) ls[64 + c] = op * op;
                __syncthreads();
                if (tid == 0) {
                    float s = 0.f;
                    for (int i = 0; i < 64; i++) s += ls[64 + i];
                    ls[128] = fmaxf(sqrtf(s), 1e-12f);
                }
                __syncthreads();
                if (tid < 64) ls[192 + c] = op / ls[128];
                __syncthreads();
                if (tid < 64) {
                    float u = 0.f;
                    for (int cp = 0; cp < 64; cp++) u = fmaf(ww[(size_t)(n * 64 + cp) * 64 + c], ls[192 + cp], u);
                    g_u[bn * 64 + c] = u;
                    g_v[bn * 64 + c] = 0.f;
                }
            } else {
                if (tid < 64) {
                    float t1 = g_T1[b * 64 + c], t2 = g_T2[b * 64 + c];
                    float s1 = t1 + 9216.f * op;
                    float s2 = t2 + 2.f * op * t1 + 9216.f * op * op;
                    s1 += __shfl_xor_sync(0xffffffffu, s1, 1); s1 += __shfl_xor_sync(0xffffffffu, s1, 2);
                    s2 += __shfl_xor_sync(0xffffffffu, s2, 1); s2 += __shfl_xor_sync(0xffffffffu, s2, 2);
                    float mu  = s1 * (1.f / 36864.f);
                    float var = s2 * (1.f / 36864.f) - mu * mu;
                    float inv = rsqrtf(var + EPSN);
                    g_A1[bn * 64 + c] = g1g[c] * inv;
                    g_D1[bn * 64 + c] = (op - mu) * inv * g1g[c] + g1b[c];
                    g_gn2s[bn * 64 + c] = 0.f; g_gn2q[bn * 64 + c] = 0.f;
                }
            }
        }
        if (it < 2) gbar(3 + 3 * it);
    }
}

// ---------------- 5: GN1(inline)+ReLU+conv3x3(64->64) via mma fp16 ---------------
// Fill: predicated uint4 copies from packed tg + in-register GN1 affine/ReLU.
// y1 written in conv2-native packed layout.
__global__ void __launch_bounds__(256, 2) k_conv1(const float* __restrict__ c1b) {
    int bn = blockIdx.z, b = bn >> 4;
    int gx0 = blockIdx.x * 16, gy0 = blockIdx.y * 16;
    int tid = threadIdx.x;
    int warp = tid >> 5, lane = tid & 31;
    int gid = lane >> 2, tg4 = lane & 3;
    int mgroup = warp & 1, ngroup = warp >> 1;

    __shared__ __half in_s[324 * 16];
    __shared__ __half w_s[9 * 64 * 16];
    __shared__ float As[64], Ds[64], Bs[64];

    if (tid < 64) { As[tid] = g_A1[bn * 64 + tid]; Ds[tid] = g_D1[bn * 64 + tid]; Bs[tid] = c1b[tid]; }

    float acc[2][8][4];
#pragma unroll
    for (int s = 0; s < 2; s++)
#pragma unroll
        for (int t = 0; t < 8; t++) { acc[s][t][0] = 0.f; acc[s][t][1] = 0.f; acc[s][t][2] = 0.f; acc[s][t][3] = 0.f; }

    int sidx[8];
#pragma unroll
    for (int t = 0; t < 8; t++) {
        int n = ngroup * 64 + t * 8 + gid;
        sidx[t] = (n >> 4) * 18 + (n & 15);
    }

    const uint4* wp4 = (const uint4*)g_wpack;
    const uint4* xsrc = (const uint4*)g_tgp;

    for (int cc4 = 0; cc4 < 4; cc4++) {
        __syncthreads();
        {
            uint4* ws4 = (uint4*)w_s;
            const uint4* src = wp4 + cc4 * 1152;
#pragma unroll
            for (int i = 0; i < 4; i++) ws4[tid + i * 256] = src[tid + i * 256];
            int idx = tid + 1024;
            if (idx < 1152) ws4[idx] = src[idx];
        }
        // input: 648 predicated uint4 copies + in-register GN1 affine/ReLU
        size_t plane = (size_t)(b * 4 + cc4) * HWC;
        for (int idx = tid; idx < 648; idx += 256) {
            int r = idx / 36, q = idx - r * 36;
            int pxr = q >> 1, hs = q & 1;
            int gy = gy0 + r - 1, gx = gx0 + pxr - 1;
            union { uint4 u; __half h[8]; } buf;
            buf.u = make_uint4(0u, 0u, 0u, 0u);
            if ((unsigned)gy < 96u && (unsigned)gx < 96u) {
                buf.u = xsrc[(plane + (size_t)gy * 96 + gx) * 2 + hs];
#pragma unroll
                for (int e = 0; e < 8; e++) {
                    int ch = cc4 * 16 + cin_of(hs * 8 + e);
                    float vv = fmaxf(fmaf(__half2float(buf.h[e]), As[ch], Ds[ch]), 0.f);
                    buf.h[e] = __float2half_rn(vv);
                }
            }
            ((uint4*)in_s)[(r * 18 + pxr) * 2 + hs] = buf.u;
        }
        __syncthreads();
#pragma unroll
        for (int ks = 0; ks < 9; ks++) {
            int toff = (ks / 3) * 18 + (ks % 3);
            uint2 afr[2][2];
#pragma unroll
            for (int s = 0; s < 2; s++) {
                int co_r0 = mgroup * 32 + s * 16 + gid;
                afr[s][0] = *(const uint2*)(w_s + (ks * 64 + co_r0) * 16 + tg4 * 4);
                afr[s][1] = *(const uint2*)(w_s + (ks * 64 + co_r0 + 8) * 16 + tg4 * 4);
            }
#pragma unroll
            for (int t = 0; t < 8; t++) {
                uint2 bb = *(const uint2*)(in_s + (toff + sidx[t]) * 16 + tg4 * 4);
#pragma unroll
                for (int s = 0; s < 2; s++) {
                    asm volatile("mma.sync.aligned.m16n8k16.row.col.f32.f16.f16.f32 "
                                 "{%0,%1,%2,%3}, {%4,%5,%6,%7}, {%8,%9}, {%0,%1,%2,%3};"
                                 : "+f"(acc[s][t][0]), "+f"(acc[s][t][1]),
                                   "+f"(acc[s][t][2]), "+f"(acc[s][t][3])
                                 : "r"(afr[s][0].x), "r"(afr[s][1].x),
                                   "r"(afr[s][0].y), "r"(afr[s][1].y),
                                   "r"(bb.x), "r"(bb.y));
                }
            }
        }
    }

    // epilogue: bias; packed fp16 store of y1; GN2 stats from the ROUNDED values
#pragma unroll
    for (int s = 0; s < 2; s++) {
        int co0 = mgroup * 32 + s * 16 + gid;
        int co1 = co0 + 8;
        int chunkb = mgroup * 2 + s;
        int sl0 = 4 * (gid >> 1) + (gid & 1);      // slot_of(gid)
        int sl1 = sl0 + 2;                         // slot_of(gid+8)
        float b0v = Bs[co0], b1v = Bs[co1];
        float s0 = 0.f, q0 = 0.f, s1 = 0.f, q1 = 0.f;
        __half* yb = g_y1p + (size_t)(bn * 4 + chunkb) * HWC * 16;
#pragma unroll
        for (int t = 0; t < 8; t++) {
            int n = ngroup * 64 + t * 8 + tg4 * 2;
            int r = n >> 4, c = n & 15;
            size_t px = (size_t)(gy0 + r) * 96 + gx0 + c;
            __half h00 = __float2half_rn(acc[s][t][0] + b0v);
            __half h01 = __float2half_rn(acc[s][t][1] + b0v);
            __half h10 = __float2half_rn(acc[s][t][2] + b1v);
            __half h11 = __float2half_rn(acc[s][t][3] + b1v);
            yb[px * 16 + sl0] = h00; yb[(px + 1) * 16 + sl0] = h01;
            yb[px * 16 + sl1] = h10; yb[(px + 1) * 16 + sl1] = h11;
            float v00 = __half2float(h00), v01 = __half2float(h01);
            float v10 = __half2float(h10), v11 = __half2float(h11);
            s0 += v00 + v01; q0 += v00 * v00 + v01 * v01;
            s1 += v10 + v11; q1 += v10 * v10 + v11 * v11;
        }
        s0 += __shfl_xor_sync(0xffffffffu, s0, 1); s0 += __shfl_xor_sync(0xffffffffu, s0, 2);
        q0 += __shfl_xor_sync(0xffffffffu, q0, 1); q0 += __shfl_xor_sync(0xffffffffu, q0, 2);
        s1 += __shfl_xor_sync(0xffffffffu, s1, 1); s1 += __shfl_xor_sync(0xffffffffu, s1, 2);
        q1 += __shfl_xor_sync(0xffffffffu, q1, 1); q1 += __shfl_xor_sync(0xffffffffu, q1, 2);
        if (tg4 == 0) {
            atomicAdd(&g_gn2s[bn * 64 + co0], s0); atomicAdd(&g_gn2q[bn * 64 + co0], q0);
            atomicAdd(&g_gn2s[bn * 64 + co1], s1); atomicAdd(&g_gn2q[bn * 64 + co1], q1);
        }
    }
}

// ---------------- 7: GN2(inline)+ReLU+conv3x3(64->1) via mma, px on M ----------
__global__ void __launch_bounds__(256) k_conv2(const float* __restrict__ c2b,
                                               const float* __restrict__ g2g,
                                               const float* __restrict__ g2b,
                                               float* __restrict__ msk) {
    int bn = blockIdx.z; int gy0 = blockIdx.y * 16, gx0 = blockIdx.x * 16;
    int tid = threadIdx.x, warp = tid >> 5, lane = tid & 31;
    int gid = lane >> 2, tg4 = lane & 3;
    __shared__ __half in_s[324 * 16];
    __shared__ __half w_s[4608];
    __shared__ float A[64], D[64];
    if (tid < 64) {
        float s = g_gn2s[bn * 64 + tid], q = g_gn2q[bn * 64 + tid];
        s += __shfl_xor_sync(0xffffffffu, s, 1); s += __shfl_xor_sync(0xffffffffu, s, 2);
        q += __shfl_xor_sync(0xffffffffu, q, 1); q += __shfl_xor_sync(0xffffffffu, q, 2);
        float mu = s * (1.f / 36864.f), var = q * (1.f / 36864.f) - mu * mu;
        float inv = rsqrtf(var + EPSN);
        A[tid] = g2g[tid] * inv;
        D[tid] = g2b[tid] - mu * inv * g2g[tid];
    }
    {
        uint4* d = (uint4*)w_s; const uint4* srcw = (const uint4*)g_w2pack;
        for (int i = tid; i < 576; i += 256) d[i] = srcw[i];
    }

    float acc[2][4];
#pragma unroll
    for (int t = 0; t < 2; t++) { acc[t][0] = 0.f; acc[t][1] = 0.f; acc[t][2] = 0.f; acc[t][3] = 0.f; }
    int s0i[2], s1i[2];
#pragma unroll
    for (int t = 0; t < 2; t++) {
        int p0 = (warp * 2 + t) * 16 + gid, p1 = p0 + 8;
        s0i[t] = (p0 >> 4) * 18 + (p0 & 15);
        s1i[t] = (p1 >> 4) * 18 + (p1 & 15);
    }
    const uint4* xsrc = (const uint4*)g_y1p;

    for (int cc4 = 0; cc4 < 4; cc4++) {
        __syncthreads();
        size_t plane = (size_t)(bn * 4 + cc4) * HWC;
        for (int idx = tid; idx < 648; idx += 256) {
            int r = idx / 36, q = idx - r * 36;
            int pxr = q >> 1, hs = q & 1;
            int gy = gy0 + r - 1, gx = gx0 + pxr - 1;
            union { uint4 u; __half h[8]; } buf;
            buf.u = make_uint4(0u, 0u, 0u, 0u);
            if ((unsigned)gy < 96u && (unsigned)gx < 96u) {
                buf.u = xsrc[(plane + (size_t)gy * 96 + gx) * 2 + hs];
#pragma unroll
                for (int e = 0; e < 8; e++) {
                    int ch = cc4 * 16 + cin_of(hs * 8 + e);
                    float vv = fmaxf(fmaf(__half2float(buf.h[e]), A[ch], D[ch]), 0.f);
                    buf.h[e] = __float2half_rn(vv);
                }
            }
            ((uint4*)in_s)[(r * 18 + pxr) * 2 + hs] = buf.u;
        }
        __syncthreads();
#pragma unroll
        for (int ks = 0; ks < 9; ks++) {
            int toff = (ks / 3) * 18 + (ks % 3);
            uint2 bb = *(const uint2*)(w_s + ((cc4 * 9 + ks) * 8 + gid) * 16 + tg4 * 4);
#pragma unroll
            for (int t = 0; t < 2; t++) {
                uint2 a01 = *(const uint2*)(in_s + (toff + s0i[t]) * 16 + tg4 * 4);
                uint2 a23 = *(const uint2*)(in_s + (toff + s1i[t]) * 16 + tg4 * 4);
                asm volatile("mma.sync.aligned.m16n8k16.row.col.f32.f16.f16.f32 "
                             "{%0,%1,%2,%3}, {%4,%5,%6,%7}, {%8,%9}, {%0,%1,%2,%3};"
                             : "+f"(acc[t][0]), "+f"(acc[t][1]), "+f"(acc[t][2]), "+f"(acc[t][3])
                             : "r"(a01.x), "r"(a23.x), "r"(a01.y), "r"(a23.y),
                               "r"(bb.x), "r"(bb.y));
            }
        }
    }
    if (tg4 == 0) {
        float bias = c2b[0];
#pragma unroll
        for (int t = 0; t < 2; t++) {
            int p0 = (warp * 2 + t) * 16 + gid, p1 = p0 + 8;
            msk[(size_t)bn * HWC + (gy0 + (p0 >> 4)) * 96 + gx0 + (p0 & 15)] = acc[t][0] + bias;
            msk[(size_t)bn * HWC + (gy0 + (p1 >> 4)) * 96 + gx0 + (p1 & 15)] = acc[t][2] + bias;
        }
    }
}

// ---------------- 8: softmax of msk + center loss + IN1 stats (single pass) ------
__global__ void k_msk_stats(const float* __restrict__ msk, float* __restrict__ out_loss) {
    int bn = blockIdx.x; int t = threadIdx.x;
    const float* m = msk + (size_t)bn * HWC;
    __shared__ float red[256];
    float mx = -1e30f;
    for (int i = t; i < HWC; i += 256) mx = fmaxf(mx, m[i]);
    mx = bmax256(mx, red);
    float se = 0.f, s1 = 0.f, s2 = 0.f;
    float ey = 0.f, ex = 0.f, ey2 = 0.f, ex2 = 0.f;
    const float st = 2.f / 95.f;
    for (int i = t; i < HWC; i += 256) {
        float v = m[i];
        float e = expf(v - mx);
        se += e; s1 += v; s2 += v * v;
        int ii = i / 96, jj = i - ii * 96;
        float yv = -1.f + st * ii, xv = -1.f + st * jj;
        ey += e * yv; ex += e * xv; ey2 += e * yv * yv; ex2 += e * xv * xv;
    }
    se = bsum256(se, red); s1 = bsum256(s1, red); s2 = bsum256(s2, red);
    ey = bsum256(ey, red); ex = bsum256(ex, red);
    ey2 = bsum256(ey2, red); ex2 = bsum256(ex2, red);
    if (t == 0) {
        float inv_se = 1.f / se;
        ey *= inv_se; ex *= inv_se; ey2 *= inv_se; ex2 *= inv_se;
        float lp = ey2 - ey * ey + ex2 - ex * ex;
        atomicAdd(out_loss, lp * (1.f / 128.f));
        float mu = s1 / 9216.f; float var = s2 / 9216.f - mu * mu;
        g_mstat[2 * bn] = mu; g_mstat[2 * bn + 1] = rsqrtf(var + EPSN);
        g_in2s[bn] = 0.f; g_in2q[bn] = 0.f;
    }
}

// ---------------- 10: IN1+ReLU+1x1(16->16) + IN2 stats ----------------
__global__ void k_gen1(const float* __restrict__ msk, const float* __restrict__ in1g,
                       const float* __restrict__ in1b, const float* __restrict__ c3w,
                       const float* __restrict__ c3b) {
    int b = blockIdx.y; int hw = blockIdx.x * 256 + threadIdx.x;
    int t = threadIdx.x;
    __shared__ float w3[256], b3[16], mus[16], invs[16], g1[16], bb1[16];
    __shared__ float bs_[16], bq_[16];
    if (t < 256) w3[t] = c3w[t];
    if (t < 16) {
        b3[t] = c3b[t]; int bn = b * 16 + t;
        mus[t] = g_mstat[2 * bn]; invs[t] = g_mstat[2 * bn + 1];
        g1[t] = in1g[t]; bb1[t] = in1b[t]; bs_[t] = 0.f; bq_[t] = 0.f;
    }
    __syncthreads();
    float r[16];
#pragma unroll
    for (int n = 0; n < 16; n++) {
        float m = msk[(size_t)(b * 16 + n) * HWC + hw];
        r[n] = fmaxf((m - mus[n]) * invs[n] * g1[n] + bb1[n], 0.f);
    }
#pragma unroll
    for (int o = 0; o < 16; o++) {
        float a = b3[o];
#pragma unroll
        for (int n = 0; n < 16; n++) a = fmaf(w3[o * 16 + n], r[n], a);
        g_g2[(size_t)(b * 16 + o) * HWC + hw] = a;
        float s = wred(a), q = wred(a * a);
        if ((t & 31) == 0) { atomicAdd(&bs_[o], s); atomicAdd(&bq_[o], q); }
    }
    __syncthreads();
    if (t < 16) { atomicAdd(&g_in2s[b * 16 + t], bs_[t]); atomicAdd(&g_in2q[b * 16 + t], bq_[t]); }
}

// ---------------- 12: IN2+ReLU+1x1(16->3)+sigmoid -> rec (IN2 stats inline) ------
__global__ void k_rec(const float* __restrict__ in2g, const float* __restrict__ in2b,
                      const float* __restrict__ c4w, const float* __restrict__ c4b,
                      float* __restrict__ out) {
    int b = blockIdx.y; int hw = blockIdx.x * 256 + threadIdx.x; int t = threadIdx.x;
    __shared__ float w4[48], mus[16], invs[16], g2[16], bb2[16];
    if (t < 48) w4[t] = c4w[t];
    if (t < 16) {
        int bo = b * 16 + t;
        float mu = g_in2s[bo] * (1.f / 9216.f);
        float var = g_in2q[bo] * (1.f / 9216.f) - mu * mu;
        mus[t] = mu; invs[t] = rsqrtf(var + EPSN);
        g2[t] = in2g[t]; bb2[t] = in2b[t];
    }
    __syncthreads();
    float x[16];
#pragma unroll
    for (int o = 0; o < 16; o++) {
        float v = g_g2[(size_t)(b * 16 + o) * HWC + hw];
        x[o] = fmaxf((v - mus[o]) * invs[o] * g2[o] + bb2[o], 0.f);
    }
#pragma unroll
    for (int o2 = 0; o2 < 3; o2++) {
        float a = c4b[o2];
#pragma unroll
        for (int o = 0; o < 16; o++) a = fmaf(w4[o2 * 16 + o], x[o], a);
        out[(size_t)(b * 3 + o2) * HWC + hw] = 1.f / (1.f + expf(-a));
    }
}

// ---------------- 13: op_out = op[bnc] * msk[bn,hw] (float4) ----------------
__global__ void k_opout(const float* __restrict__ msk, float* __restrict__ out) {
    int bn = blockIdx.y; int i4 = blockIdx.x * 256 + threadIdx.x;   // 0..2303
    __shared__ float ops[64];
    if (threadIdx.x < 64) ops[threadIdx.x] = g_op[bn * 64 + threadIdx.x];
    __syncthreads();
    float4 m4 = ((const float4*)(msk + (size_t)bn * HWC))[i4];
    float* ob = out + (size_t)bn * 64 * HWC;
#pragma unroll 8
    for (int c = 0; c < 64; c++) {
        float s = ops[c];
        float4 r; r.x = s * m4.x; r.y = s * m4.y; r.z = s * m4.z; r.w = s * m4.w;
        ((float4*)(ob + (size_t)c * HWC))[i4] = r;
    }
}

// ---------------- launch ----------------
extern "C" void kernel_launch(void* const* d_in, const int* in_sizes, int n_in,
                              void* d_out, int out_size) {
    const float* sr   = (const float*)d_in[0];
    const float* tg   = (const float*)d_in[1];
    const float* ww   = (const float*)d_in[2];
    const float* wb   = (const float*)d_in[3];
    const float* gn1g = (const float*)d_in[4];
    const float* gn1b = (const float*)d_in[5];
    const float* c1w  = (const float*)d_in[6];
    const float* c1b  = (const float*)d_in[7];
    const float* gn2g = (const float*)d_in[8];
    const float* gn2b = (const float*)d_in[9];
    const float* c2w  = (const float*)d_in[10];
    const float* c2b  = (const float*)d_in[11];
    const float* in1g = (const float*)d_in[12];
    const float* in1b = (const float*)d_in[13];
    const float* c3w  = (const float*)d_in[14];
    const float* c3b  = (const float*)d_in[15];
    const float* in2g = (const float*)d_in[16];
    const float* in2b = (const float*)d_in[17];
    const float* c4w  = (const float*)d_in[18];
    const float* c4b  = (const float*)d_in[19];
    float* out = (float*)d_out;
    float* out_msk  = out + 75497472;
    float* out_rec  = out + 76677120;
    float* out_loss = out + 76898304;
    float* out_cof  = out + 76898305;

    k_colsum<<<656, 256>>>(sr, tg, c1w, c2w, out_loss);
    k_tgpack<<<dim3(36, 8), 256>>>(tg);
    k_route<<<dim3(36, 8), 256>>>(sr, ww, wb, gn1g, gn1b, out_cof);
    k_conv1<<<dim3(6, 6, 128), 256>>>(c1b);
    k_conv2<<<dim3(6, 6, 128), 256>>>(c2b, gn2g, gn2b, out_msk);
    k_msk_stats<<<128, 256>>>(out_msk, out_loss);
    k_gen1<<<dim3(36, 8), 256>>>(out_msk, in1g, in1b, c3w, c3b);
    k_rec<<<dim3(36, 8), 256>>>(in2g, in2b, c4w, c4b, out_rec);
    k_opout<<<dim3(9, 128), 256>>>(out_msk, out);
}

// round 17
// speedup vs baseline: 2.5309x; 1.0349x over previous
#include <cuda_runtime.h>
#include <cuda_fp16.h>
#include <cstdint>
#include <cstddef>

#define HWC 9216
#define EPSN 1e-5f

// ---------------- scratch (__device__ globals; no allocation) ----------------
__device__ __align__(16) __half g_y1p[75497472]; // y1 packed [bn][chunk4][px][slot16]
__device__ __align__(16) __half g_tgp[4718592];  // tg packed [b][chunk4][px][slot16]
__device__ float g_g2[1179648];       // gen-block intermediate [8,16,9216]
__device__ float g_tsum[512];         // sum_hw sr [8,64]
__device__ float g_T1[512];           // sum_hw tg
__device__ float g_T2[512];           // sum_hw tg^2
__device__ float g_op[8192];          // [128,64]
__device__ float g_u[8192];           // W^T opn
__device__ float g_v[8192];           // sum_hw sr*cof
__device__ float g_A1[8192];          // GN1 affine scale
__device__ float g_D1[8192];          // GN1 affine shift
__device__ float g_gn2s[8192];
__device__ float g_gn2q[8192];
__device__ float g_mstat[256];        // per-bn (mu, invstd) of msk
__device__ float g_in2s[128];
__device__ float g_in2q[128];
__device__ float2 g_pms[4608];        // per-(bn,blk) online softmax partials (m,s)
__device__ unsigned g_barc[16];       // grid-barrier counters
__device__ __align__(16) __half g_wpack[36864];   // packed fp16 conv1 weights
__device__ __align__(16) __half g_w2pack[4608];   // conv2 weights: [chunk4][tap9][n8][slot16]

// ---------------- helpers ----------------
__device__ __forceinline__ float wred(float v) {
#pragma unroll
    for (int o = 16; o > 0; o >>= 1) v += __shfl_xor_sync(0xffffffffu, v, o);
    return v;
}
__device__ __forceinline__ float bsum256(float v, float* red) {
    int t = threadIdx.x; red[t] = v; __syncthreads();
#pragma unroll
    for (int s = 128; s > 0; s >>= 1) { if (t < s) red[t] += red[t + s]; __syncthreads(); }
    float r = red[0]; __syncthreads(); return r;
}
__device__ __forceinline__ float bmax256(float v, float* red) {
    int t = threadIdx.x; red[t] = v; __syncthreads();
#pragma unroll
    for (int s = 128; s > 0; s >>= 1) { if (t < s) red[t] = fmaxf(red[t], red[t + s]); __syncthreads(); }
    float r = red[0]; __syncthreads(); return r;
}
__device__ __forceinline__ int slot_of(int c) {   // cin-slot permutation
    return 4 * ((c & 7) >> 1) + ((((c >> 3) & 1) << 1) | (c & 1));
}
__device__ __forceinline__ int cin_of(int slot) { // inverse permutation
    int p = slot >> 2, pos = slot & 3;
    return 2 * p + (pos & 1) + ((pos >> 1) << 3);
}
// grid barrier: all 288 CTAs of k_route arrive. Residency guaranteed by occupancy.
__device__ __forceinline__ void gbar(int id) {
    __syncthreads();
    if (threadIdx.x == 0) {
        __threadfence();
        atomicAdd(&g_barc[id], 1u);
        while (*(volatile unsigned*)&g_barc[id] < 288u) __nanosleep(64);
        __threadfence();
    }
    __syncthreads();
}

// ---------------- 1: colsum (blocks 0..511) + weight packs + barrier reset -------
__global__ void k_colsum(const float* __restrict__ sr, const float* __restrict__ tg,
                         const float* __restrict__ c1w, const float* __restrict__ c2w,
                         float* __restrict__ out_loss) {
    if (blockIdx.x >= 512) {
        int idx = (blockIdx.x - 512) * 256 + threadIdx.x;   // 0..36863
        if (idx == 0) out_loss[0] = 0.f;
        if (idx < 16) g_barc[idx] = 0u;
        {   // conv1 weights
            int slot = idx & 15;
            int co = (idx >> 4) & 63;
            int rest = idx >> 10;
            int tap = rest % 9, chunk = rest / 9;
            int cin = cin_of(slot);
            g_wpack[idx] = __float2half_rn(c1w[(size_t)(co * 64 + chunk * 16 + cin) * 9 + tap]);
        }
        if (idx < 4608) {   // conv2 weights, B-fragment layout, n=0 real / n>0 zero
            int slot = idx & 15;
            int n = (idx >> 4) & 7;
            int rest = idx >> 7;               // chunk*9 + tap
            int tap = rest % 9, chunk = rest / 9;
            int cin = cin_of(slot);
            float wv = (n == 0) ? c2w[(chunk * 16 + cin) * 9 + tap] : 0.f;
            g_w2pack[idx] = __float2half_rn(wv);
        }
        return;
    }
    int bc = blockIdx.x;
    const float4* ps = (const float4*)(sr + (size_t)bc * HWC);
    const float4* pt = (const float4*)(tg + (size_t)bc * HWC);
    float s0 = 0.f, s1 = 0.f, s2 = 0.f;
    for (int i = threadIdx.x; i < 2304; i += 256) {
        float4 a = ps[i], b = pt[i];
        s0 += a.x + a.y + a.z + a.w;
        s1 += b.x + b.y + b.z + b.w;
        s2 += b.x * b.x + b.y * b.y + b.z * b.z + b.w * b.w;
    }
    __shared__ float red[256];
    s0 = bsum256(s0, red); s1 = bsum256(s1, red); s2 = bsum256(s2, red);
    if (threadIdx.x == 0) { g_tsum[bc] = s0; g_T1[bc] = s1; g_T2[bc] = s2; }
}

// ---------------- 1b: pack tg to fp16 conv-native layout ----------------
__global__ void k_tgpack(const float* __restrict__ tg) {
    int b = blockIdx.y; int px = blockIdx.x * 256 + threadIdx.x;
    const float* tp = tg + (size_t)b * 64 * HWC + px;
#pragma unroll
    for (int chunk = 0; chunk < 4; chunk++) {
        union { uint4 u[2]; __half h[16]; } buf;
#pragma unroll
        for (int cin = 0; cin < 16; cin++)
            buf.h[slot_of(cin)] = __float2half_rn(tp[(size_t)(chunk * 16 + cin) * HWC]);
        uint4* dst = (uint4*)(g_tgp + ((size_t)(b * 4 + chunk) * HWC + px) * 16);
        dst[0] = buf.u[0]; dst[1] = buf.u[1];
    }
}

// ---------------- 2: fused dynamic-routing loop (persistent, grid barriers) ------
__global__ void __launch_bounds__(256, 2) k_route(
    const float* __restrict__ sr, const float* __restrict__ ww,
    const float* __restrict__ wb, const float* __restrict__ g1g,
    const float* __restrict__ g1b, float* __restrict__ extra)
{
    __shared__ float us[1024];
    __shared__ float ls[16 * 257];
    __shared__ float2 Ms[16];
    int b = blockIdx.y, blk = blockIdx.x;
    int tid = threadIdx.x;
    int hw = blk * 256 + tid;
    int w = tid >> 5, lane = tid & 31;

    // ---- C0 ----
    if (blk < 16) {
        int n = blk, bn = b * 16 + n, c = tid;
        float op = 0.f;
        if (tid < 64) ls[tid] = g_tsum[b * 64 + tid];
        __syncthreads();
        if (tid < 64) {
            const float* wr = ww + (size_t)(n * 64 + c) * 64;
            float a = 0.f;
#pragma unroll 8
            for (int cp = 0; cp < 64; cp++) a = fmaf(wr[cp], ls[cp], a);
            op = a + wb[n * 64 + c] * 9216.f;
            g_op[bn * 64 + c] = op;
            ls[64 + c] = op * op;
        }
        __syncthreads();
        if (tid == 0) {
            float s = 0.f;
            for (int i = 0; i < 64; i++) s += ls[64 + i];
            ls[128] = fmaxf(sqrtf(s), 1e-12f);
        }
        __syncthreads();
        if (tid < 64) ls[192 + c] = op / ls[128];
        __syncthreads();
        if (tid < 64) {
            float u = 0.f;
            for (int cp = 0; cp < 64; cp++) u = fmaf(ww[(size_t)(n * 64 + cp) * 64 + c], ls[192 + cp], u);
            g_u[bn * 64 + c] = u;
            g_v[bn * 64 + c] = 0.f;
        }
    }
    gbar(0);

    for (int it = 0; it < 3; it++) {
        // ---- A ----
        __syncthreads();
        for (int i = tid; i < 1024; i += 256) us[i] = g_u[b * 1024 + i];
        __syncthreads();
        float acc[16];
#pragma unroll
        for (int n = 0; n < 16; n++) acc[n] = 0.f;
        {
            const float* sp = sr + (size_t)b * 64 * HWC + hw;
            for (int c = 0; c < 64; c++) {
                float v = sp[(size_t)c * HWC];
#pragma unroll
                for (int n = 0; n < 16; n++) acc[n] = fmaf(us[n * 64 + c], v, acc[n]);
            }
        }
#pragma unroll
        for (int n = 0; n < 16; n++) ls[n * 257 + tid] = acc[n];
        __syncthreads();
#pragma unroll
        for (int nn = 0; nn < 2; nn++) {
            int n = w * 2 + nn;
            float v[8]; float mx = -1e30f;
#pragma unroll
            for (int j = 0; j < 8; j++) { v[j] = ls[n * 257 + lane + 32 * j]; mx = fmaxf(mx, v[j]); }
#pragma unroll
            for (int o = 16; o > 0; o >>= 1) mx = fmaxf(mx, __shfl_xor_sync(0xffffffffu, mx, o));
            float s = 0.f;
#pragma unroll
            for (int j = 0; j < 8; j++) s += expf(v[j] - mx);
            s = wred(s);
            if (lane == 0) g_pms[(b * 16 + n) * 36 + blk] = make_float2(mx, s);
        }
        gbar(1 + 3 * it);

        // ---- B ----
        if (tid < 16) {
            const float2* pp = g_pms + (b * 16 + tid) * 36;
            float M = -1e30f;
#pragma unroll
            for (int i = 0; i < 36; i++) M = fmaxf(M, pp[i].x);
            float S = 0.f;
#pragma unroll
            for (int i = 0; i < 36; i++) S += pp[i].y * expf(pp[i].x - M);
            Ms[tid] = make_float2(M, 1.f / S);
        }
        __syncthreads();
        for (int idx = tid; idx < 4096; idx += 256) {
            int n = idx >> 8, k = idx & 255;
            float c = expf(ls[n * 257 + k] - Ms[n].x) * Ms[n].y;
            ls[n * 257 + k] = c;
            if (it == 2) extra[(size_t)(b * 16 + n) * HWC + blk * 256 + k] = c;
        }
        __syncthreads();
        for (int c = w; c < 64; c += 8) {
            const float* sp = sr + (size_t)(b * 64 + c) * HWC + blk * 256;
            float a[16];
#pragma unroll
            for (int n = 0; n < 16; n++) a[n] = 0.f;
#pragma unroll
            for (int kk = 0; kk < 8; kk++) {
                int k = lane + kk * 32;
                float s = sp[k];
#pragma unroll
                for (int n = 0; n < 16; n++) a[n] = fmaf(s, ls[n * 257 + k], a[n]);
            }
#pragma unroll
            for (int n = 0; n < 16; n++) {
                float r = wred(a[n]);
                if (lane == 0) atomicAdd(&g_v[(b * 16 + n) * 64 + c], r);
            }
        }
        gbar(2 + 3 * it);

        // ---- C ----
        if (blk < 16) {
            int n = blk, bn = b * 16 + n, c = tid;
            float op = 0.f;
            if (tid < 64) ls[tid] = g_v[bn * 64 + tid];
            __syncthreads();
            if (tid < 64) {
                const float* wr = ww + (size_t)(n * 64 + c) * 64;
                float a = 0.f;
#pragma unroll 8
                for (int cp = 0; cp < 64; cp++) a = fmaf(wr[cp], ls[cp], a);
                op = a + wb[n * 64 + c];
                g_op[bn * 64 + c] = op;
            }
            __syncthreads();
            if (it < 2) {
                if (tid < 64) ls[64 + c] = op * op;
                __syncthreads();
                if (tid == 0) {
                    float s = 0.f;
                    for (int i = 0; i < 64; i++) s += ls[64 + i];
                    ls[128] = fmaxf(sqrtf(s), 1e-12f);
                }
                __syncthreads();
                if (tid < 64) ls[192 + c] = op / ls[128];
                __syncthreads();
                if (tid < 64) {
                    float u = 0.f;
                    for (int cp = 0; cp < 64; cp++) u = fmaf(ww[(size_t)(n * 64 + cp) * 64 + c], ls[192 + cp], u);
                    g_u[bn * 64 + c] = u;
                    g_v[bn * 64 + c] = 0.f;
                }
            } else {
                if (tid < 64) {
                    float t1 = g_T1[b * 64 + c], t2 = g_T2[b * 64 + c];
                    float s1 = t1 + 9216.f * op;
                    float s2 = t2 + 2.f * op * t1 + 9216.f * op * op;
                    s1 += __shfl_xor_sync(0xffffffffu, s1, 1); s1 += __shfl_xor_sync(0xffffffffu, s1, 2);
                    s2 += __shfl_xor_sync(0xffffffffu, s2, 1); s2 += __shfl_xor_sync(0xffffffffu, s2, 2);
                    float mu  = s1 * (1.f / 36864.f);
                    float var = s2 * (1.f / 36864.f) - mu * mu;
                    float inv = rsqrtf(var + EPSN);
                    g_A1[bn * 64 + c] = g1g[c] * inv;
                    g_D1[bn * 64 + c] = (op - mu) * inv * g1g[c] + g1b[c];
                    g_gn2s[bn * 64 + c] = 0.f; g_gn2q[bn * 64 + c] = 0.f;
                }
            }
        }
        if (it < 2) gbar(3 + 3 * it);
    }
}

// ---------------- 5: GN1(inline)+ReLU+conv3x3(64->64) via mma fp16 ---------------
// Slot-permuted affine tables (no per-element permutation ALU in fill);
// epilogue stages y1 tiles in smem (reusing w_s) and writes coalesced STG.128.
__global__ void __launch_bounds__(256, 2) k_conv1(const float* __restrict__ c1b) {
    int bn = blockIdx.z, b = bn >> 4;
    int gx0 = blockIdx.x * 16, gy0 = blockIdx.y * 16;
    int tid = threadIdx.x;
    int warp = tid >> 5, lane = tid & 31;
    int gid = lane >> 2, tg4 = lane & 3;
    int mgroup = warp & 1, ngroup = warp >> 1;

    __shared__ __half in_s[324 * 16];
    __shared__ __half w_s[9 * 64 * 16];   // also reused as epilogue staging (2x 8KB)
    __shared__ float As[64], Ds[64], Bs[64];

    if (tid < 64) {
        int pidx = (tid >> 4) * 16 + slot_of(tid & 15);   // slot-permuted position
        As[pidx] = g_A1[bn * 64 + tid];
        Ds[pidx] = g_D1[bn * 64 + tid];
        Bs[tid] = c1b[tid];
    }

    float acc[2][8][4];
#pragma unroll
    for (int s = 0; s < 2; s++)
#pragma unroll
        for (int t = 0; t < 8; t++) { acc[s][t][0] = 0.f; acc[s][t][1] = 0.f; acc[s][t][2] = 0.f; acc[s][t][3] = 0.f; }

    int sidx[8];
#pragma unroll
    for (int t = 0; t < 8; t++) {
        int n = ngroup * 64 + t * 8 + gid;
        sidx[t] = (n >> 4) * 18 + (n & 15);
    }

    const uint4* wp4 = (const uint4*)g_wpack;
    const uint4* xsrc = (const uint4*)g_tgp;

    for (int cc4 = 0; cc4 < 4; cc4++) {
        __syncthreads();
        {
            uint4* ws4 = (uint4*)w_s;
            const uint4* src = wp4 + cc4 * 1152;
#pragma unroll
            for (int i = 0; i < 4; i++) ws4[tid + i * 256] = src[tid + i * 256];
            int idx = tid + 1024;
            if (idx < 1152) ws4[idx] = src[idx];
        }
        // input: 648 predicated uint4 copies + in-register GN1 affine/ReLU (slot order)
        size_t plane = (size_t)(b * 4 + cc4) * HWC;
        for (int idx = tid; idx < 648; idx += 256) {
            int r = idx / 36, q = idx - r * 36;
            int pxr = q >> 1, hs = q & 1;
            int gy = gy0 + r - 1, gx = gx0 + pxr - 1;
            union { uint4 u; __half h[8]; } buf;
            buf.u = make_uint4(0u, 0u, 0u, 0u);
            if ((unsigned)gy < 96u && (unsigned)gx < 96u) {
                buf.u = xsrc[(plane + (size_t)gy * 96 + gx) * 2 + hs];
#pragma unroll
                for (int e = 0; e < 8; e++) {
                    int ps = cc4 * 16 + hs * 8 + e;   // slot-order index
                    float vv = fmaxf(fmaf(__half2float(buf.h[e]), As[ps], Ds[ps]), 0.f);
                    buf.h[e] = __float2half_rn(vv);
                }
            }
            ((uint4*)in_s)[(r * 18 + pxr) * 2 + hs] = buf.u;
        }
        __syncthreads();
#pragma unroll
        for (int ks = 0; ks < 9; ks++) {
            int toff = (ks / 3) * 18 + (ks % 3);
            uint2 afr[2][2];
#pragma unroll
            for (int s = 0; s < 2; s++) {
                int co_r0 = mgroup * 32 + s * 16 + gid;
                afr[s][0] = *(const uint2*)(w_s + (ks * 64 + co_r0) * 16 + tg4 * 4);
                afr[s][1] = *(const uint2*)(w_s + (ks * 64 + co_r0 + 8) * 16 + tg4 * 4);
            }
#pragma unroll
            for (int t = 0; t < 8; t++) {
                uint2 bb = *(const uint2*)(in_s + (toff + sidx[t]) * 16 + tg4 * 4);
#pragma unroll
                for (int s = 0; s < 2; s++) {
                    asm volatile("mma.sync.aligned.m16n8k16.row.col.f32.f16.f16.f32 "
                                 "{%0,%1,%2,%3}, {%4,%5,%6,%7}, {%8,%9}, {%0,%1,%2,%3};"
                                 : "+f"(acc[s][t][0]), "+f"(acc[s][t][1]),
                                   "+f"(acc[s][t][2]), "+f"(acc[s][t][3])
                                 : "r"(afr[s][0].x), "r"(afr[s][1].x),
                                   "r"(afr[s][0].y), "r"(afr[s][1].y),
                                   "r"(bb.x), "r"(bb.y));
                }
            }
        }
    }

    // epilogue: two passes; stage chunk tiles into w_s, then coalesced STG.128.
    int sl0 = 4 * (gid >> 1) + (gid & 1);      // slot_of(gid)
    int sl1 = sl0 + 2;                         // slot_of(gid+8)
#pragma unroll
    for (int s = 0; s < 2; s++) {
        int co0 = mgroup * 32 + s * 16 + gid;
        int co1 = co0 + 8;
        float b0v = Bs[co0], b1v = Bs[co1];
        __half* tile = w_s + mgroup * 4096;    // 256px x 16slots halves
        float s0 = 0.f, q0 = 0.f, s1 = 0.f, q1 = 0.f;
        __syncthreads();   // w_s free (mainloop or previous STG pass done)
#pragma unroll
        for (int t = 0; t < 8; t++) {
            int n = ngroup * 64 + t * 8 + tg4 * 2;
            __half h00 = __float2half_rn(acc[s][t][0] + b0v);
            __half h01 = __float2half_rn(acc[s][t][1] + b0v);
            __half h10 = __float2half_rn(acc[s][t][2] + b1v);
            __half h11 = __float2half_rn(acc[s][t][3] + b1v);
            tile[n * 16 + sl0] = h00; tile[(n + 1) * 16 + sl0] = h01;
            tile[n * 16 + sl1] = h10; tile[(n + 1) * 16 + sl1] = h11;
            float v00 = __half2float(h00), v01 = __half2float(h01);
            float v10 = __half2float(h10), v11 = __half2float(h11);
            s0 += v00 + v01; q0 += v00 * v00 + v01 * v01;
            s1 += v10 + v11; q1 += v10 * v10 + v11 * v11;
        }
        s0 += __shfl_xor_sync(0xffffffffu, s0, 1); s0 += __shfl_xor_sync(0xffffffffu, s0, 2);
        q0 += __shfl_xor_sync(0xffffffffu, q0, 1); q0 += __shfl_xor_sync(0xffffffffu, q0, 2);
        s1 += __shfl_xor_sync(0xffffffffu, s1, 1); s1 += __shfl_xor_sync(0xffffffffu, s1, 2);
        q1 += __shfl_xor_sync(0xffffffffu, q1, 1); q1 += __shfl_xor_sync(0xffffffffu, q1, 2);
        if (tg4 == 0) {
            atomicAdd(&g_gn2s[bn * 64 + co0], s0); atomicAdd(&g_gn2q[bn * 64 + co0], q0);
            atomicAdd(&g_gn2s[bn * 64 + co1], s1); atomicAdd(&g_gn2q[bn * 64 + co1], q1);
        }
        __syncthreads();   // staging complete
        // vector store both mgroup tiles (chunks s and 2+s): 1024 uint4
#pragma unroll
        for (int i = 0; i < 4; i++) {
            int idx = tid + i * 256;           // 0..1023
            int tl = idx >> 9;                 // which tile (mgroup)
            int w9 = idx & 511;
            int r = w9 >> 5, c32 = w9 & 31;
            int cb = tl * 2 + s;
            uint4 v = ((const uint4*)w_s)[tl * 512 + w9];
            size_t gbase = ((size_t)(bn * 4 + cb) * HWC + (size_t)(gy0 + r) * 96 + gx0) * 16;
            ((uint4*)(g_y1p + gbase))[c32] = v;
        }
    }
}

// ---------------- 7: GN2(inline)+ReLU+conv3x3(64->1) via mma, px on M ----------
__global__ void __launch_bounds__(256) k_conv2(const float* __restrict__ c2b,
                                               const float* __restrict__ g2g,
                                               const float* __restrict__ g2b,
                                               float* __restrict__ msk) {
    int bn = blockIdx.z; int gy0 = blockIdx.y * 16, gx0 = blockIdx.x * 16;
    int tid = threadIdx.x, warp = tid >> 5, lane = tid & 31;
    int gid = lane >> 2, tg4 = lane & 3;
    __shared__ __half in_s[324 * 16];
    __shared__ __half w_s[4608];
    __shared__ float A[64], D[64];
    if (tid < 64) {  // GN2 finalize (natural-c shuffles), store slot-permuted
        float s = g_gn2s[bn * 64 + tid], q = g_gn2q[bn * 64 + tid];
        s += __shfl_xor_sync(0xffffffffu, s, 1); s += __shfl_xor_sync(0xffffffffu, s, 2);
        q += __shfl_xor_sync(0xffffffffu, q, 1); q += __shfl_xor_sync(0xffffffffu, q, 2);
        float mu = s * (1.f / 36864.f), var = q * (1.f / 36864.f) - mu * mu;
        float inv = rsqrtf(var + EPSN);
        int pidx = (tid >> 4) * 16 + slot_of(tid & 15);
        A[pidx] = g2g[tid] * inv;
        D[pidx] = g2b[tid] - mu * inv * g2g[tid];
    }
    {
        uint4* d = (uint4*)w_s; const uint4* srcw = (const uint4*)g_w2pack;
        for (int i = tid; i < 576; i += 256) d[i] = srcw[i];
    }

    float acc[2][4];
#pragma unroll
    for (int t = 0; t < 2; t++) { acc[t][0] = 0.f; acc[t][1] = 0.f; acc[t][2] = 0.f; acc[t][3] = 0.f; }
    int s0i[2], s1i[2];
#pragma unroll
    for (int t = 0; t < 2; t++) {
        int p0 = (warp * 2 + t) * 16 + gid, p1 = p0 + 8;
        s0i[t] = (p0 >> 4) * 18 + (p0 & 15);
        s1i[t] = (p1 >> 4) * 18 + (p1 & 15);
    }
    const uint4* xsrc = (const uint4*)g_y1p;

    for (int cc4 = 0; cc4 < 4; cc4++) {
        __syncthreads();
        size_t plane = (size_t)(bn * 4 + cc4) * HWC;
        for (int idx = tid; idx < 648; idx += 256) {
            int r = idx / 36, q = idx - r * 36;
            int pxr = q >> 1, hs = q & 1;
            int gy = gy0 + r - 1, gx = gx0 + pxr - 1;
            union { uint4 u; __half h[8]; } buf;
            buf.u = make_uint4(0u, 0u, 0u, 0u);
            if ((unsigned)gy < 96u && (unsigned)gx < 96u) {
                buf.u = xsrc[(plane + (size_t)gy * 96 + gx) * 2 + hs];
#pragma unroll
                for (int e = 0; e < 8; e++) {
                    int ps = cc4 * 16 + hs * 8 + e;   // slot-order index
                    float vv = fmaxf(fmaf(__half2float(buf.h[e]), A[ps], D[ps]), 0.f);
                    buf.h[e] = __float2half_rn(vv);
                }
            }
            ((uint4*)in_s)[(r * 18 + pxr) * 2 + hs] = buf.u;
        }
        __syncthreads();
#pragma unroll
        for (int ks = 0; ks < 9; ks++) {
            int toff = (ks / 3) * 18 + (ks % 3);
            uint2 bb = *(const uint2*)(w_s + ((cc4 * 9 + ks) * 8 + gid) * 16 + tg4 * 4);
#pragma unroll
            for (int t = 0; t < 2; t++) {
                uint2 a01 = *(const uint2*)(in_s + (toff + s0i[t]) * 16 + tg4 * 4);
                uint2 a23 = *(const uint2*)(in_s + (toff + s1i[t]) * 16 + tg4 * 4);
                asm volatile("mma.sync.aligned.m16n8k16.row.col.f32.f16.f16.f32 "
                             "{%0,%1,%2,%3}, {%4,%5,%6,%7}, {%8,%9}, {%0,%1,%2,%3};"
                             : "+f"(acc[t][0]), "+f"(acc[t][1]), "+f"(acc[t][2]), "+f"(acc[t][3])
                             : "r"(a01.x), "r"(a23.x), "r"(a01.y), "r"(a23.y),
                               "r"(bb.x), "r"(bb.y));
            }
        }
    }
    if (tg4 == 0) {
        float bias = c2b[0];
#pragma unroll
        for (int t = 0; t < 2; t++) {
            int p0 = (warp * 2 + t) * 16 + gid, p1 = p0 + 8;
            msk[(size_t)bn * HWC + (gy0 + (p0 >> 4)) * 96 + gx0 + (p0 & 15)] = acc[t][0] + bias;
            msk[(size_t)bn * HWC + (gy0 + (p1 >> 4)) * 96 + gx0 + (p1 & 15)] = acc[t][2] + bias;
        }
    }
}

// ---------------- 8: softmax of msk + center loss + IN1 stats (single pass) ------
__global__ void k_msk_stats(const float* __restrict__ msk, float* __restrict__ out_loss) {
    int bn = blockIdx.x; int t = threadIdx.x;
    const float* m = msk + (size_t)bn * HWC;
    __shared__ float red[256];
    float mx = -1e30f;
    for (int i = t; i < HWC; i += 256) mx = fmaxf(mx, m[i]);
    mx = bmax256(mx, red);
    float se = 0.f, s1 = 0.f, s2 = 0.f;
    float ey = 0.f, ex = 0.f, ey2 = 0.f, ex2 = 0.f;
    const float st = 2.f / 95.f;
    for (int i = t; i < HWC; i += 256) {
        float v = m[i];
        float e = expf(v - mx);
        se += e; s1 += v; s2 += v * v;
        int ii = i / 96, jj = i - ii * 96;
        float yv = -1.f + st * ii, xv = -1.f + st * jj;
        ey += e * yv; ex += e * xv; ey2 += e * yv * yv; ex2 += e * xv * xv;
    }
    se = bsum256(se, red); s1 = bsum256(s1, red); s2 = bsum256(s2, red);
    ey = bsum256(ey, red); ex = bsum256(ex, red);
    ey2 = bsum256(ey2, red); ex2 = bsum256(ex2, red);
    if (t == 0) {
        float inv_se = 1.f / se;
        ey *= inv_se; ex *= inv_se; ey2 *= inv_se; ex2 *= inv_se;
        float lp = ey2 - ey * ey + ex2 - ex * ex;
        atomicAdd(out_loss, lp * (1.f / 128.f));
        float mu = s1 / 9216.f; float var = s2 / 9216.f - mu * mu;
        g_mstat[2 * bn] = mu; g_mstat[2 * bn + 1] = rsqrtf(var + EPSN);
        g_in2s[bn] = 0.f; g_in2q[bn] = 0.f;
    }
}

// ---------------- 10: IN1+ReLU+1x1(16->16) + IN2 stats ----------------
__global__ void k_gen1(const float* __restrict__ msk, const float* __restrict__ in1g,
                       const float* __restrict__ in1b, const float* __restrict__ c3w,
                       const float* __restrict__ c3b) {
    int b = blockIdx.y; int hw = blockIdx.x * 256 + threadIdx.x;
    int t = threadIdx.x;
    __shared__ float w3[256], b3[16], mus[16], invs[16], g1[16], bb1[16];
    __shared__ float bs_[16], bq_[16];
    if (t < 256) w3[t] = c3w[t];
    if (t < 16) {
        b3[t] = c3b[t]; int bn = b * 16 + t;
        mus[t] = g_mstat[2 * bn]; invs[t] = g_mstat[2 * bn + 1];
        g1[t] = in1g[t]; bb1[t] = in1b[t]; bs_[t] = 0.f; bq_[t] = 0.f;
    }
    __syncthreads();
    float r[16];
#pragma unroll
    for (int n = 0; n < 16; n++) {
        float m = msk[(size_t)(b * 16 + n) * HWC + hw];
        r[n] = fmaxf((m - mus[n]) * invs[n] * g1[n] + bb1[n], 0.f);
    }
#pragma unroll
    for (int o = 0; o < 16; o++) {
        float a = b3[o];
#pragma unroll
        for (int n = 0; n < 16; n++) a = fmaf(w3[o * 16 + n], r[n], a);
        g_g2[(size_t)(b * 16 + o) * HWC + hw] = a;
        float s = wred(a), q = wred(a * a);
        if ((t & 31) == 0) { atomicAdd(&bs_[o], s); atomicAdd(&bq_[o], q); }
    }
    __syncthreads();
    if (t < 16) { atomicAdd(&g_in2s[b * 16 + t], bs_[t]); atomicAdd(&g_in2q[b * 16 + t], bq_[t]); }
}

// ---------------- 12: IN2+ReLU+1x1(16->3)+sigmoid -> rec (IN2 stats inline) ------
__global__ void k_rec(const float* __restrict__ in2g, const float* __restrict__ in2b,
                      const float* __restrict__ c4w, const float* __restrict__ c4b,
                      float* __restrict__ out) {
    int b = blockIdx.y; int hw = blockIdx.x * 256 + threadIdx.x; int t = threadIdx.x;
    __shared__ float w4[48], mus[16], invs[16], g2[16], bb2[16];
    if (t < 48) w4[t] = c4w[t];
    if (t < 16) {
        int bo = b * 16 + t;
        float mu = g_in2s[bo] * (1.f / 9216.f);
        float var = g_in2q[bo] * (1.f / 9216.f) - mu * mu;
        mus[t] = mu; invs[t] = rsqrtf(var + EPSN);
        g2[t] = in2g[t]; bb2[t] = in2b[t];
    }
    __syncthreads();
    float x[16];
#pragma unroll
    for (int o = 0; o < 16; o++) {
        float v = g_g2[(size_t)(b * 16 + o) * HWC + hw];
        x[o] = fmaxf((v - mus[o]) * invs[o] * g2[o] + bb2[o], 0.f);
    }
#pragma unroll
    for (int o2 = 0; o2 < 3; o2++) {
        float a = c4b[o2];
#pragma unroll
        for (int o = 0; o < 16; o++) a = fmaf(w4[o2 * 16 + o], x[o], a);
        out[(size_t)(b * 3 + o2) * HWC + hw] = 1.f / (1.f + expf(-a));
    }
}

// ---------------- 13: op_out = op[bnc] * msk[bn,hw] (float4) ----------------
__global__ void k_opout(const float* __restrict__ msk, float* __restrict__ out) {
    int bn = blockIdx.y; int i4 = blockIdx.x * 256 + threadIdx.x;   // 0..2303
    __shared__ float ops[64];
    if (threadIdx.x < 64) ops[threadIdx.x] = g_op[bn * 64 + threadIdx.x];
    __syncthreads();
    float4 m4 = ((const float4*)(msk + (size_t)bn * HWC))[i4];
    float* ob = out + (size_t)bn * 64 * HWC;
#pragma unroll 8
    for (int c = 0; c < 64; c++) {
        float s = ops[c];
        float4 r; r.x = s * m4.x; r.y = s * m4.y; r.z = s * m4.z; r.w = s * m4.w;
        ((float4*)(ob + (size_t)c * HWC))[i4] = r;
    }
}

// ---------------- launch ----------------
extern "C" void kernel_launch(void* const* d_in, const int* in_sizes, int n_in,
                              void* d_out, int out_size) {
    const float* sr   = (const float*)d_in[0];
    const float* tg   = (const float*)d_in[1];
    const float* ww   = (const float*)d_in[2];
    const float* wb   = (const float*)d_in[3];
    const float* gn1g = (const float*)d_in[4];
    const float* gn1b = (const float*)d_in[5];
    const float* c1w  = (const float*)d_in[6];
    const float* c1b  = (const float*)d_in[7];
    const float* gn2g = (const float*)d_in[8];
    const float* gn2b = (const float*)d_in[9];
    const float* c2w  = (const float*)d_in[10];
    const float* c2b  = (const float*)d_in[11];
    const float* in1g = (const float*)d_in[12];
    const float* in1b = (const float*)d_in[13];
    const float* c3w  = (const float*)d_in[14];
    const float* c3b  = (const float*)d_in[15];
    const float* in2g = (const float*)d_in[16];
    const float* in2b = (const float*)d_in[17];
    const float* c4w  = (const float*)d_in[18];
    const float* c4b  = (const float*)d_in[19];
    float* out = (float*)d_out;
    float* out_msk  = out + 75497472;
    float* out_rec  = out + 76677120;
    float* out_loss = out + 76898304;
    float* out_cof  = out + 76898305;

    k_colsum<<<656, 256>>>(sr, tg, c1w, c2w, out_loss);
    k_tgpack<<<dim3(36, 8), 256>>>(tg);
    k_route<<<dim3(36, 8), 256>>>(sr, ww, wb, gn1g, gn1b, out_cof);
    k_conv1<<<dim3(6, 6, 128), 256>>>(c1b);
    k_conv2<<<dim3(6, 6, 128), 256>>>(c2b, gn2g, gn2b, out_msk);
    k_msk_stats<<<128, 256>>>(out_msk, out_loss);
    k_gen1<<<dim3(36, 8), 256>>>(out_msk, in1g, in1b, c3w, c3b);
    k_rec<<<dim3(36, 8), 256>>>(in2g, in2b, c4w, c4b, out_rec);
    k_opout<<<dim3(9, 128), 256>>>(out_msk, out);
}